// round 7
// baseline (speedup 1.0000x reference)
#include <cuda_runtime.h>
#include <cuda_bf16.h>
#include <cstdint>
#include <cstddef>

// ---------------------------------------------------------------------------
// AttentionalPropagation, B=2, D=256, H=4, dim=64, N=M=4096.
// R7: flash keeps P in registers (S-frag == PV A-frag identity);
//     gemms 128x64 tiles for full-chip grids; raw-bit tf32 loads everywhere.
// ---------------------------------------------------------------------------

#define BB 2
#define DD 256
#define HH 4

__device__ __nv_bfloat16 g_q[BB * HH * 4096 * 64];  // [b][h][n][di], pre-scaled
__device__ __nv_bfloat16 g_k[BB * HH * 4096 * 64];  // [b][h][m][di]
__device__ __nv_bfloat16 g_v[BB * HH * 64 * 4096];  // [b][h][di][m] (transposed)
__device__ float g_attn[BB * DD * 4096];            // (B, D, N), tf32-rounded
__device__ float g_msg [BB * DD * 4096];            // tf32-rounded
__device__ float g_h   [BB * 2 * DD * 4096];        // (B, 2D, N)
__device__ float g_wts [655360];                    // tf32-rounded weights
__device__ float g_xr  [BB * DD * 4096];            // tf32-rounded x
__device__ float g_sr  [BB * DD * 4096];            // tf32-rounded source

#define OFF_WQ 0
#define OFF_WK 65536
#define OFF_WV 131072
#define OFF_WM 196608
#define OFF_W1 262144
#define OFF_W2 524288

#define QSCALE (0.125f * 1.44269504088896340736f)   // 1/sqrt(64) * log2(e)

// ============================ PTX helpers ==================================
__device__ __forceinline__ uint32_t smem_u32(const void* p) {
    uint32_t a;
    asm("{ .reg .u64 t; cvta.to.shared.u64 t, %1; cvt.u32.u64 %0, t; }"
        : "=r"(a) : "l"(p));
    return a;
}
__device__ __forceinline__ uint32_t f2tf(float x) {
    uint32_t r; asm("cvt.rna.tf32.f32 %0, %1;" : "=r"(r) : "f"(x)); return r;
}
__device__ __forceinline__ float rtf(float x) { return __uint_as_float(f2tf(x)); }
__device__ __forceinline__ float ex2(float x) {
    float r; asm("ex2.approx.f32 %0, %1;" : "=f"(r) : "f"(x)); return r;
}
__device__ __forceinline__ uint32_t packbf(float lo, float hi) {
    __nv_bfloat162 h = __floats2bfloat162_rn(lo, hi);
    return *reinterpret_cast<uint32_t*>(&h);
}
// tf32 m16n8k8
__device__ __forceinline__ void mma8(float* d, const uint32_t* a,
                                     uint32_t b0, uint32_t b1) {
    asm volatile("mma.sync.aligned.m16n8k8.row.col.f32.tf32.tf32.f32 "
        "{%0,%1,%2,%3}, {%4,%5,%6,%7}, {%8,%9}, {%0,%1,%2,%3};"
        : "+f"(d[0]), "+f"(d[1]), "+f"(d[2]), "+f"(d[3])
        : "r"(a[0]), "r"(a[1]), "r"(a[2]), "r"(a[3]), "r"(b0), "r"(b1));
}
// bf16 m16n8k16
__device__ __forceinline__ void mma16(float* d, const uint32_t* a,
                                      uint32_t b0, uint32_t b1) {
    asm volatile("mma.sync.aligned.m16n8k16.row.col.f32.bf16.bf16.f32 "
        "{%0,%1,%2,%3}, {%4,%5,%6,%7}, {%8,%9}, {%0,%1,%2,%3};"
        : "+f"(d[0]), "+f"(d[1]), "+f"(d[2]), "+f"(d[3])
        : "r"(a[0]), "r"(a[1]), "r"(a[2]), "r"(a[3]), "r"(b0), "r"(b1));
}
__device__ __forceinline__ void cp16(uint32_t s, const void* g) {
    asm volatile("cp.async.ca.shared.global [%0], [%1], 16;" :: "r"(s), "l"(g));
}
#define CP_COMMIT() asm volatile("cp.async.commit_group;" ::: "memory")
#define CP_WAIT(n)  asm volatile("cp.async.wait_group %0;" :: "n"(n) : "memory")

// ---------------------------------------------------------------------------
// producer rounding kernels (deterministic)
// ---------------------------------------------------------------------------
__global__ void round_weights(const float* __restrict__ wq, const float* __restrict__ wk,
                              const float* __restrict__ wv, const float* __restrict__ wm,
                              const float* __restrict__ w1, const float* __restrict__ w2,
                              float* __restrict__ dst)
{
    int i = blockIdx.x * 256 + threadIdx.x;
    if (i >= 655360) return;
    float v;
    if      (i < OFF_WK) v = wq[i - OFF_WQ];
    else if (i < OFF_WV) v = wk[i - OFF_WK];
    else if (i < OFF_WM) v = wv[i - OFF_WM + OFF_WM - OFF_WV];   // = wv[i-OFF_WV]
    else if (i < OFF_W1) v = wm[i - OFF_WM];
    else if (i < OFF_W2) v = w1[i - OFF_W1];
    else                 v = w2[i - OFF_W2];
    dst[i] = rtf(v);
}

__global__ void round_inputs(const float* __restrict__ x, const float* __restrict__ src,
                             float* __restrict__ xr, float* __restrict__ sr, int n)
{
    int i = (blockIdx.x * 256 + threadIdx.x) * 4;
    if (i >= n) return;
    float4 a = *reinterpret_cast<const float4*>(x + i);
    float4 b = *reinterpret_cast<const float4*>(src + i);
    a.x = rtf(a.x); a.y = rtf(a.y); a.z = rtf(a.z); a.w = rtf(a.w);
    b.x = rtf(b.x); b.y = rtf(b.y); b.z = rtf(b.z); b.w = rtf(b.w);
    *reinterpret_cast<float4*>(xr + i) = a;
    *reinterpret_cast<float4*>(sr + i) = b;
}

// ---------------------------------------------------------------------------
// bf16 flash attention, P register-resident.
// grid (N/128, H, B), 128 threads (4 warps), 32 q-rows/warp.
// The S C-fragment (rows g/g+8, cols j*8+2tg..+1) IS the PV A-fragment for
// k-step j/2 -> exp'd scores pack straight into mma A regs; no P smem.
// ---------------------------------------------------------------------------
#define LDB 72          // bf16 pitch for K / V / Q tiles
#define LDT 132         // fp32 pitch for O^T staging

__global__ void __launch_bounds__(128)
flash_attn_bf(const __nv_bfloat16* __restrict__ q, const __nv_bfloat16* __restrict__ k,
              const __nv_bfloat16* __restrict__ v, float* __restrict__ attn,
              int N, int M)
{
    extern __shared__ char smb[];
    __nv_bfloat16* Ks = reinterpret_cast<__nv_bfloat16*>(smb);            // [2][64][LDB]
    __nv_bfloat16* Vs = reinterpret_cast<__nv_bfloat16*>(smb + 18432);    // [2][64][LDB]
    __nv_bfloat16* Qs = reinterpret_cast<__nv_bfloat16*>(smb + 36864);    // [128][LDB]
    float* OT = reinterpret_cast<float*>(smb);                            // [64][LDT]

    const int b  = blockIdx.z, h = blockIdx.y;
    const int n0 = blockIdx.x * 128;
    const int bh = b * HH + h;
    const int t  = threadIdx.x;
    const int wid = t >> 5, lane = t & 31;
    const int g = lane >> 2, tg = lane & 3;
    const int wr = wid * 32;

    const __nv_bfloat16* Kg = k + (size_t)bh * M * 64;
    const __nv_bfloat16* Vg = v + (size_t)bh * 64 * M;

    // prefetch K/V tile 0
    {
        uint32_t kd = smem_u32(Ks), vd = smem_u32(Vs);
        #pragma unroll
        for (int i = 0; i < 4; i++) {
            int idx = t + i * 128;
            int r = idx >> 3, c = (idx & 7) * 8;
            cp16(kd + (uint32_t)(r * LDB + c) * 2, Kg + r * 64 + c);
            cp16(vd + (uint32_t)(r * LDB + c) * 2, Vg + (size_t)r * M + c);
        }
        CP_COMMIT();
    }

    // stage Q
    {
        const __nv_bfloat16* Qg = q + ((size_t)bh * N + n0) * 64;
        #pragma unroll
        for (int i = 0; i < 8; i++) {
            int idx = t + i * 128;
            int r = idx >> 3, c = (idx & 7) * 8;
            *reinterpret_cast<uint4*>(Qs + r * LDB + c) =
                *reinterpret_cast<const uint4*>(Qg + r * 64 + c);
        }
    }
    __syncthreads();

    // persistent Q fragments
    uint32_t Qf[2][4][4];
    #pragma unroll
    for (int mt = 0; mt < 2; mt++) {
        int r0 = wr + mt * 16 + g;
        #pragma unroll
        for (int kk = 0; kk < 4; kk++) {
            Qf[mt][kk][0] = *reinterpret_cast<uint32_t*>(Qs + (r0    ) * LDB + kk * 16 + 2 * tg);
            Qf[mt][kk][1] = *reinterpret_cast<uint32_t*>(Qs + (r0 + 8) * LDB + kk * 16 + 2 * tg);
            Qf[mt][kk][2] = *reinterpret_cast<uint32_t*>(Qs + (r0    ) * LDB + kk * 16 + 2 * tg + 8);
            Qf[mt][kk][3] = *reinterpret_cast<uint32_t*>(Qs + (r0 + 8) * LDB + kk * 16 + 2 * tg + 8);
        }
    }
    __syncthreads();

    float Of[8][2][4] = {};
    float lrow[2][2]  = {};

    const int nT = M / 64;
    for (int tt = 0; tt < nT; tt++) {
        const __nv_bfloat16* Kc = Ks + (tt & 1) * 64 * LDB;
        const __nv_bfloat16* Vc = Vs + (tt & 1) * 64 * LDB;

        if (tt + 1 < nT) {
            uint32_t kd = smem_u32(Ks + ((tt + 1) & 1) * 64 * LDB);
            uint32_t vd = smem_u32(Vs + ((tt + 1) & 1) * 64 * LDB);
            const __nv_bfloat16* Kn = Kg + (size_t)(tt + 1) * 64 * 64;
            const __nv_bfloat16* Vn = Vg + (size_t)(tt + 1) * 64;
            #pragma unroll
            for (int i = 0; i < 4; i++) {
                int idx = t + i * 128;
                int r = idx >> 3, c = (idx & 7) * 8;
                cp16(kd + (uint32_t)(r * LDB + c) * 2, Kn + r * 64 + c);
                cp16(vd + (uint32_t)(r * LDB + c) * 2, Vn + (size_t)r * M + c);
            }
            CP_COMMIT();
            CP_WAIT(1);
        } else {
            CP_WAIT(0);
        }
        __syncthreads();

        // S = Q K^T
        float Sc[8][2][4] = {};
        #pragma unroll
        for (int j = 0; j < 8; j++) {
            const __nv_bfloat16* Kr = Kc + (j * 8 + g) * LDB + 2 * tg;
            #pragma unroll
            for (int kk = 0; kk < 4; kk++) {
                uint32_t b0 = *reinterpret_cast<const uint32_t*>(Kr + kk * 16);
                uint32_t b1 = *reinterpret_cast<const uint32_t*>(Kr + kk * 16 + 8);
                mma16(Sc[j][0], Qf[0][kk], b0, b1);
                mma16(Sc[j][1], Qf[1][kk], b0, b1);
            }
        }

        // exp2 + row-sum + pack straight into PV A-fragments (no smem!)
        uint32_t Pa[4][2][4];
        #pragma unroll
        for (int mt = 0; mt < 2; mt++) {
            #pragma unroll
            for (int j = 0; j < 8; j++) {
                float e0 = ex2(Sc[j][mt][0]);
                float e1 = ex2(Sc[j][mt][1]);
                float e2 = ex2(Sc[j][mt][2]);
                float e3 = ex2(Sc[j][mt][3]);
                lrow[mt][0] += e0 + e1;
                lrow[mt][1] += e2 + e3;
                int kk = j >> 1, hf = (j & 1) * 2;
                Pa[kk][mt][hf    ] = packbf(e0, e1);   // row r0   half
                Pa[kk][mt][hf + 1] = packbf(e2, e3);   // row r0+8 half
            }
        }

        // O += P V  (V^T in smem)
        #pragma unroll
        for (int kk = 0; kk < 4; kk++) {
            #pragma unroll
            for (int j = 0; j < 8; j++) {
                const __nv_bfloat16* Vr = Vc + (j * 8 + g) * LDB + kk * 16 + 2 * tg;
                uint32_t b0 = *reinterpret_cast<const uint32_t*>(Vr);
                uint32_t b1 = *reinterpret_cast<const uint32_t*>(Vr + 8);
                mma16(Of[j][0], Pa[kk][0], b0, b1);
                mma16(Of[j][1], Pa[kk][1], b0, b1);
            }
        }
        __syncthreads();
    }

    // finalize l
    #pragma unroll
    for (int mt = 0; mt < 2; mt++)
        #pragma unroll
        for (int r = 0; r < 2; r++) {
            float s = lrow[mt][r];
            s += __shfl_xor_sync(0xffffffffu, s, 1);
            s += __shfl_xor_sync(0xffffffffu, s, 2);
            lrow[mt][r] = 1.0f / s;
        }

    __syncthreads();
    #pragma unroll
    for (int j = 0; j < 8; j++) {
        #pragma unroll
        for (int mt = 0; mt < 2; mt++) {
            int r0 = wr + mt * 16 + g;
            OT[(j * 8 + 2 * tg    ) * LDT + r0    ] = Of[j][mt][0] * lrow[mt][0];
            OT[(j * 8 + 2 * tg + 1) * LDT + r0    ] = Of[j][mt][1] * lrow[mt][0];
            OT[(j * 8 + 2 * tg    ) * LDT + r0 + 8] = Of[j][mt][2] * lrow[mt][1];
            OT[(j * 8 + 2 * tg + 1) * LDT + r0 + 8] = Of[j][mt][3] * lrow[mt][1];
        }
    }
    __syncthreads();

    // coalesced tf32-rounded store into (B, D, N), channel = di*H + h
    #pragma unroll
    for (int cc = 0; cc < 16; cc++) {
        int di = wid * 16 + cc;
        float4 val = *reinterpret_cast<const float4*>(OT + di * LDT + lane * 4);
        val.x = rtf(val.x); val.y = rtf(val.y); val.z = rtf(val.z); val.w = rtf(val.w);
        *reinterpret_cast<float4*>(
            attn + ((size_t)(b * DD + di * HH + h)) * N + n0 + lane * 4) = val;
    }
}

// ---------------------------------------------------------------------------
// tf32 GEMM body, tile 128(o) x 64(n), BK=32, double-buffered cp.async.
// 8 warps = 4(o) x 2(n); warp tile 32x32 (mt=2, nt=4). All loads raw-bit
// (W and X both pre-rounded to tf32 by producers).
// ---------------------------------------------------------------------------
#define LDWM 36
#define LDXN 72

struct GemmOut {
    float acc[2][4][4];
    int o0, n0, wo, wn, g, tg;
};

__device__ __forceinline__ void gemm_body(
    const float* __restrict__ W, const float* __restrict__ X0, int C0,
    const float* __restrict__ X1, int b, int IC, int N,
    int o0, int n0, float* sm, GemmOut& R)
{
    float* Ws = sm;                       // [2][128][LDWM]
    float* Xs = sm + 2 * 128 * LDWM;      // [2][32][LDXN]

    const int t  = threadIdx.x;
    const int wid = t >> 5, lane = t & 31;
    R.g = lane >> 2; R.tg = lane & 3;
    R.wo = (wid & 3) * 32;
    R.wn = (wid >> 2) * 32;
    R.o0 = o0; R.n0 = n0;

    auto stage = [&](int buf, int k0) {
        uint32_t wd = smem_u32(Ws + buf * 128 * LDWM);
        uint32_t xd = smem_u32(Xs + buf * 32 * LDXN);
        #pragma unroll
        for (int i = 0; i < 4; i++) {
            int idx = t + i * 256;
            int r = idx >> 3, c = (idx & 7) * 4;
            cp16(wd + (uint32_t)(r * LDWM + c) * 4,
                 W + (size_t)(o0 + r) * IC + k0 + c);
        }
        #pragma unroll
        for (int i = 0; i < 2; i++) {
            int idx = t + i * 256;
            int r = idx >> 4, c = (idx & 15) * 4;
            int ch = k0 + r;
            const float* src = (ch < C0)
                ? (X0 + ((size_t)b * C0 + ch) * N)
                : (X1 + ((size_t)b * (IC - C0) + (ch - C0)) * N);
            cp16(xd + (uint32_t)(r * LDXN + c) * 4, src + n0 + c);
        }
        CP_COMMIT();
    };

    stage(0, 0);
    #pragma unroll
    for (int a = 0; a < 2; a++)
        #pragma unroll
        for (int c = 0; c < 4; c++)
            #pragma unroll
            for (int d = 0; d < 4; d++) R.acc[a][c][d] = 0.f;

    const int nK = IC / 32;
    for (int kt = 0; kt < nK; kt++) {
        if (kt + 1 < nK) { stage((kt + 1) & 1, (kt + 1) * 32); CP_WAIT(1); }
        else             { CP_WAIT(0); }
        __syncthreads();
        const float* Wc = Ws + (kt & 1) * 128 * LDWM;
        const float* Xc = Xs + (kt & 1) * 32 * LDXN;

        #pragma unroll
        for (int ks = 0; ks < 4; ks++) {
            uint32_t Af[2][4];
            #pragma unroll
            for (int mt = 0; mt < 2; mt++) {
                int r0 = R.wo + mt * 16 + R.g;
                Af[mt][0] = __float_as_uint(Wc[(r0    ) * LDWM + ks * 8 + R.tg]);
                Af[mt][1] = __float_as_uint(Wc[(r0 + 8) * LDWM + ks * 8 + R.tg]);
                Af[mt][2] = __float_as_uint(Wc[(r0    ) * LDWM + ks * 8 + R.tg + 4]);
                Af[mt][3] = __float_as_uint(Wc[(r0 + 8) * LDWM + ks * 8 + R.tg + 4]);
            }
            #pragma unroll
            for (int nt = 0; nt < 4; nt++) {
                uint32_t b0 = __float_as_uint(Xc[(ks * 8 + R.tg    ) * LDXN + R.wn + nt * 8 + R.g]);
                uint32_t b1 = __float_as_uint(Xc[(ks * 8 + R.tg + 4) * LDXN + R.wn + nt * 8 + R.g]);
                mma8(R.acc[0][nt], Af[0], b0, b1);
                mma8(R.acc[1][nt], Af[1], b0, b1);
            }
        }
        __syncthreads();
    }
}

// generic projection: (B,OC,N) layout; round_out controls tf32 epilogue rounding
__global__ void __launch_bounds__(256)
gemm_tc(const float* __restrict__ W, const float* __restrict__ bias,
        const float* __restrict__ X0, int C0, const float* __restrict__ X1,
        float* __restrict__ out, int OC, int IC, int N, int round_out)
{
    extern __shared__ float sm[];
    GemmOut R;
    gemm_body(W, X0, C0, X1, blockIdx.z, IC, N,
              blockIdx.y * 128, blockIdx.x * 64, sm, R);

    #pragma unroll
    for (int mt = 0; mt < 2; mt++) {
        int o_g  = R.o0 + R.wo + mt * 16 + R.g;
        int o_g8 = o_g + 8;
        float bg  = bias[o_g];
        float bg8 = bias[o_g8];
        #pragma unroll
        for (int nt = 0; nt < 4; nt++) {
            int n = R.n0 + R.wn + nt * 8 + 2 * R.tg;
            float c0 = R.acc[mt][nt][0] + bg,  c1 = R.acc[mt][nt][1] + bg;
            float c2 = R.acc[mt][nt][2] + bg8, c3 = R.acc[mt][nt][3] + bg8;
            if (round_out) { c0 = rtf(c0); c1 = rtf(c1); c2 = rtf(c2); c3 = rtf(c3); }
            *reinterpret_cast<float2*>(out + ((size_t)blockIdx.z * OC + o_g ) * N + n) =
                make_float2(c0, c1);
            *reinterpret_cast<float2*>(out + ((size_t)blockIdx.z * OC + o_g8) * N + n) =
                make_float2(c2, c3);
        }
    }
}

// fused Q/K/V projection: grid (N/64, D/128, 6); z = which*2 + b.
__global__ void __launch_bounds__(256)
gemm_qkv(const float* __restrict__ wts,
         const float* __restrict__ bq, const float* __restrict__ bk,
         const float* __restrict__ bv,
         const float* __restrict__ x, const float* __restrict__ src,
         __nv_bfloat16* __restrict__ qp, __nv_bfloat16* __restrict__ kp,
         __nv_bfloat16* __restrict__ vp, int N)
{
    extern __shared__ float sm[];
    const int z = blockIdx.z;
    const int which = z >> 1;
    const int b = z & 1;
    const float* W    = wts + which * 65536;
    const float* bias = (which == 0) ? bq : (which == 1) ? bk : bv;
    const float* X    = (which == 0) ? x : src;
    const float oscale = (which == 0) ? QSCALE : 1.0f;

    GemmOut R;
    gemm_body(W, X, DD, nullptr, b, DD, N, blockIdx.y * 128, blockIdx.x * 64, sm, R);

    #pragma unroll
    for (int mt = 0; mt < 2; mt++) {
        int o_g  = R.o0 + R.wo + mt * 16 + R.g;
        int o_g8 = o_g + 8;
        float bg  = bias[o_g];
        float bg8 = bias[o_g8];
        #pragma unroll
        for (int nt = 0; nt < 4; nt++) {
            int n = R.n0 + R.wn + nt * 8 + 2 * R.tg;
            float c0 = (R.acc[mt][nt][0] + bg)  * oscale;
            float c1 = (R.acc[mt][nt][1] + bg)  * oscale;
            float c2 = (R.acc[mt][nt][2] + bg8) * oscale;
            float c3 = (R.acc[mt][nt][3] + bg8) * oscale;
            int h0 = o_g & 3,  d0 = o_g >> 2;
            int h1 = o_g8 & 3, d1 = o_g8 >> 2;
            if (which < 2) {
                __nv_bfloat16* out = (which == 0) ? qp : kp;
                out[(((size_t)b * HH + h0) * N + n    ) * 64 + d0] = __float2bfloat16_rn(c0);
                out[(((size_t)b * HH + h0) * N + n + 1) * 64 + d0] = __float2bfloat16_rn(c1);
                out[(((size_t)b * HH + h1) * N + n    ) * 64 + d1] = __float2bfloat16_rn(c2);
                out[(((size_t)b * HH + h1) * N + n + 1) * 64 + d1] = __float2bfloat16_rn(c3);
            } else {
                *reinterpret_cast<uint32_t*>(
                    vp + (((size_t)b * HH + h0) * 64 + d0) * N + n) = packbf(c0, c1);
                *reinterpret_cast<uint32_t*>(
                    vp + (((size_t)b * HH + h1) * 64 + d1) * N + n) = packbf(c2, c3);
            }
        }
    }
}

// ---------------------------------------------------------------------------
// InstanceNorm1d (affine=False, biased var) + ReLU, in place, tf32-rounded out.
// ---------------------------------------------------------------------------
__global__ void instnorm_relu(float* __restrict__ hb, int N)
{
    int row = blockIdx.x;
    float* p = hb + (size_t)row * N;

    float s = 0.f, s2 = 0.f;
    for (int i = threadIdx.x * 4; i < N; i += blockDim.x * 4) {
        float4 v = *reinterpret_cast<const float4*>(p + i);
        s  += (v.x + v.y) + (v.z + v.w);
        s2 += v.x * v.x + v.y * v.y + v.z * v.z + v.w * v.w;
    }
    #pragma unroll
    for (int off = 16; off > 0; off >>= 1) {
        s  += __shfl_xor_sync(0xffffffffu, s,  off);
        s2 += __shfl_xor_sync(0xffffffffu, s2, off);
    }
    __shared__ float sh[16];
    int wid = threadIdx.x >> 5, lid = threadIdx.x & 31;
    if (lid == 0) { sh[wid] = s; sh[wid + 8] = s2; }
    __syncthreads();
    if (threadIdx.x < 32) {
        s  = (lid < 8) ? sh[lid]     : 0.f;
        s2 = (lid < 8) ? sh[lid + 8] : 0.f;
        #pragma unroll
        for (int off = 4; off > 0; off >>= 1) {
            s  += __shfl_xor_sync(0xffffffffu, s,  off);
            s2 += __shfl_xor_sync(0xffffffffu, s2, off);
        }
        if (lid == 0) { sh[0] = s; sh[1] = s2; }
    }
    __syncthreads();
    float mean = sh[0] / (float)N;
    float var  = sh[1] / (float)N - mean * mean;
    float inv  = rsqrtf(var + 1e-5f);
    for (int i = threadIdx.x * 4; i < N; i += blockDim.x * 4) {
        float4 v = *reinterpret_cast<const float4*>(p + i);
        v.x = rtf(fmaxf(0.f, (v.x - mean) * inv));
        v.y = rtf(fmaxf(0.f, (v.y - mean) * inv));
        v.z = rtf(fmaxf(0.f, (v.z - mean) * inv));
        v.w = rtf(fmaxf(0.f, (v.w - mean) * inv));
        *reinterpret_cast<float4*>(p + i) = v;
    }
}

// ---------------------------------------------------------------------------
extern "C" void kernel_launch(void* const* d_in, const int* in_sizes, int n_in,
                              void* d_out, int out_size)
{
    const float* x   = (const float*)d_in[0];
    const float* src = (const float*)d_in[1];
    const float* Wq  = (const float*)d_in[2];
    const float* bq  = (const float*)d_in[3];
    const float* Wk  = (const float*)d_in[4];
    const float* bk  = (const float*)d_in[5];
    const float* Wv  = (const float*)d_in[6];
    const float* bv  = (const float*)d_in[7];
    const float* Wm  = (const float*)d_in[8];
    const float* bm  = (const float*)d_in[9];
    const float* W1  = (const float*)d_in[10];
    const float* b1  = (const float*)d_in[11];
    const float* W2  = (const float*)d_in[12];
    const float* b2  = (const float*)d_in[13];

    const int B = BB, D = DD;
    const int N = in_sizes[0] / (B * D);
    const int M = in_sizes[1] / (B * D);

    __nv_bfloat16 *qp, *kp, *vp;
    float *attnp, *msgp, *hp, *wts, *xr, *sr;
    cudaGetSymbolAddress((void**)&qp,    g_q);
    cudaGetSymbolAddress((void**)&kp,    g_k);
    cudaGetSymbolAddress((void**)&vp,    g_v);
    cudaGetSymbolAddress((void**)&attnp, g_attn);
    cudaGetSymbolAddress((void**)&msgp,  g_msg);
    cudaGetSymbolAddress((void**)&hp,    g_h);
    cudaGetSymbolAddress((void**)&wts,   g_wts);
    cudaGetSymbolAddress((void**)&xr,    g_xr);
    cudaGetSymbolAddress((void**)&sr,    g_sr);

    const int gsmem = (2 * 128 * LDWM + 2 * 32 * LDXN) * (int)sizeof(float);  // 55296
    const int fsmem = 36864 + 128 * LDB * 2;                                   // 55296
    cudaFuncSetAttribute(gemm_tc,  cudaFuncAttributeMaxDynamicSharedMemorySize, gsmem);
    cudaFuncSetAttribute(gemm_qkv, cudaFuncAttributeMaxDynamicSharedMemorySize, gsmem);
    cudaFuncSetAttribute(flash_attn_bf, cudaFuncAttributeMaxDynamicSharedMemorySize, fsmem);

    // 0. producer-side tf32 rounding
    round_weights<<<(655360 + 255) / 256, 256>>>(Wq, Wk, Wv, Wm, W1, W2, wts);
    const int nIn = B * D * N;
    round_inputs<<<(nIn / 4 + 255) / 256, 256>>>(x, src, xr, sr, nIn);

    // 1. fused Q/K/V projections (bf16; Q pre-scaled; V transposed)
    gemm_qkv<<<dim3(N / 64, D / 128, 3 * B), 256, gsmem>>>(
        wts, bq, bk, bv, xr, sr, qp, kp, vp, N);

    // 2. fused bf16 flash attention (P register-resident)
    flash_attn_bf<<<dim3(N / 128, HH, B), 128, fsmem>>>(qp, kp, vp, attnp, N, M);

    // 3. message projection (tf32-rounded out)
    gemm_tc<<<dim3(N / 64, D / 128, B), 256, gsmem>>>(
        wts + OFF_WM, bm, attnp, D, nullptr, msgp, D, D, N, 1);

    // 4. MLP first layer on virtual concat [x; message]
    gemm_tc<<<dim3(N / 64, (2 * D) / 128, B), 256, gsmem>>>(
        wts + OFF_W1, b1, xr, D, msgp, hp, 2 * D, 2 * D, N, 0);

    // 5. InstanceNorm + ReLU (tf32-rounded out)
    instnorm_relu<<<B * 2 * D, 256>>>(hp, N);

    // 6. final projection -> d_out (no rounding)
    gemm_tc<<<dim3(N / 64, D / 128, B), 256, gsmem>>>(
        wts + OFF_W2, b2, hp, 2 * D, nullptr, (float*)d_out, D, 2 * D, N, 0);
}

// round 8
// speedup vs baseline: 1.0426x; 1.0426x over previous
#include <cuda_runtime.h>
#include <cuda_bf16.h>
#include <cstdint>
#include <cstddef>

// ---------------------------------------------------------------------------
// AttentionalPropagation, B=2, D=256, H=4, dim=64, N=M=4096.
// R8: message GEMM folded into W1 (Wcat = [W1x | W1m@Wm]); gemms back to
//     128x128 tiles; flash S-mma loop reordered for 16-way ILP.
// ---------------------------------------------------------------------------

#define BB 2
#define DD 256
#define HH 4

__device__ __nv_bfloat16 g_q[BB * HH * 4096 * 64];  // [b][h][n][di], pre-scaled
__device__ __nv_bfloat16 g_k[BB * HH * 4096 * 64];  // [b][h][m][di]
__device__ __nv_bfloat16 g_v[BB * HH * 64 * 4096];  // [b][h][di][m] (transposed)
__device__ float g_attn[BB * DD * 4096];            // (B, D, N), tf32-rounded
__device__ float g_h   [BB * 2 * DD * 4096];        // (B, 2D, N)
__device__ float g_wts [655360];                    // tf32-rounded weights
__device__ float g_xr  [BB * DD * 4096];            // tf32-rounded x
__device__ float g_sr  [BB * DD * 4096];            // tf32-rounded source
__device__ float g_wcat[512 * 512];                 // [W1x | W1m@Wm], tf32
__device__ float g_bf  [512];                       // W1m@bm + b1

#define OFF_WQ 0
#define OFF_WK 65536
#define OFF_WV 131072
#define OFF_WM 196608
#define OFF_W1 262144
#define OFF_W2 524288

#define QSCALE (0.125f * 1.44269504088896340736f)   // 1/sqrt(64) * log2(e)

// ============================ PTX helpers ==================================
__device__ __forceinline__ uint32_t smem_u32(const void* p) {
    uint32_t a;
    asm("{ .reg .u64 t; cvta.to.shared.u64 t, %1; cvt.u32.u64 %0, t; }"
        : "=r"(a) : "l"(p));
    return a;
}
__device__ __forceinline__ uint32_t f2tf(float x) {
    uint32_t r; asm("cvt.rna.tf32.f32 %0, %1;" : "=r"(r) : "f"(x)); return r;
}
__device__ __forceinline__ float rtf(float x) { return __uint_as_float(f2tf(x)); }
__device__ __forceinline__ float ex2(float x) {
    float r; asm("ex2.approx.f32 %0, %1;" : "=f"(r) : "f"(x)); return r;
}
__device__ __forceinline__ uint32_t packbf(float lo, float hi) {
    __nv_bfloat162 h = __floats2bfloat162_rn(lo, hi);
    return *reinterpret_cast<uint32_t*>(&h);
}
// tf32 m16n8k8
__device__ __forceinline__ void mma8(float* d, const uint32_t* a,
                                     uint32_t b0, uint32_t b1) {
    asm volatile("mma.sync.aligned.m16n8k8.row.col.f32.tf32.tf32.f32 "
        "{%0,%1,%2,%3}, {%4,%5,%6,%7}, {%8,%9}, {%0,%1,%2,%3};"
        : "+f"(d[0]), "+f"(d[1]), "+f"(d[2]), "+f"(d[3])
        : "r"(a[0]), "r"(a[1]), "r"(a[2]), "r"(a[3]), "r"(b0), "r"(b1));
}
// bf16 m16n8k16
__device__ __forceinline__ void mma16(float* d, const uint32_t* a,
                                      uint32_t b0, uint32_t b1) {
    asm volatile("mma.sync.aligned.m16n8k16.row.col.f32.bf16.bf16.f32 "
        "{%0,%1,%2,%3}, {%4,%5,%6,%7}, {%8,%9}, {%0,%1,%2,%3};"
        : "+f"(d[0]), "+f"(d[1]), "+f"(d[2]), "+f"(d[3])
        : "r"(a[0]), "r"(a[1]), "r"(a[2]), "r"(a[3]), "r"(b0), "r"(b1));
}
__device__ __forceinline__ void cp16(uint32_t s, const void* g) {
    asm volatile("cp.async.ca.shared.global [%0], [%1], 16;" :: "r"(s), "l"(g));
}
#define CP_COMMIT() asm volatile("cp.async.commit_group;" ::: "memory")
#define CP_WAIT(n)  asm volatile("cp.async.wait_group %0;" :: "n"(n) : "memory")

// ---------------------------------------------------------------------------
// producer rounding kernels (deterministic)
// ---------------------------------------------------------------------------
__global__ void round_weights(const float* __restrict__ wq, const float* __restrict__ wk,
                              const float* __restrict__ wv, const float* __restrict__ wm,
                              const float* __restrict__ w1, const float* __restrict__ w2,
                              float* __restrict__ dst)
{
    int i = blockIdx.x * 256 + threadIdx.x;
    if (i >= 655360) return;
    float v;
    if      (i < OFF_WK) v = wq[i - OFF_WQ];
    else if (i < OFF_WV) v = wk[i - OFF_WK];
    else if (i < OFF_WM) v = wv[i - OFF_WV];
    else if (i < OFF_W1) v = wm[i - OFF_WM];
    else if (i < OFF_W2) v = w1[i - OFF_W1];
    else                 v = w2[i - OFF_W2];
    dst[i] = rtf(v);
}

__global__ void round_inputs(const float* __restrict__ x, const float* __restrict__ src,
                             float* __restrict__ xr, float* __restrict__ sr, int n)
{
    int i = (blockIdx.x * 256 + threadIdx.x) * 4;
    if (i >= n) return;
    float4 a = *reinterpret_cast<const float4*>(x + i);
    float4 b = *reinterpret_cast<const float4*>(src + i);
    a.x = rtf(a.x); a.y = rtf(a.y); a.z = rtf(a.z); a.w = rtf(a.w);
    b.x = rtf(b.x); b.y = rtf(b.y); b.z = rtf(b.z); b.w = rtf(b.w);
    *reinterpret_cast<float4*>(xr + i) = a;
    *reinterpret_cast<float4*>(sr + i) = b;
}

// ---------------------------------------------------------------------------
// fold message projection: Wcat = [W1x | rtf(W1m @ Wm)], bf = W1m @ bm + b1.
// grid 512 blocks (one per output row o), 256 threads (one per col j).
// W1 row stride 512; reads tf32-rounded weights.
// ---------------------------------------------------------------------------
__global__ void fuse_w1(const float* __restrict__ wts, const float* __restrict__ b1,
                        const float* __restrict__ bm,
                        float* __restrict__ wcat, float* __restrict__ bf)
{
    const float* w1 = wts + OFF_W1;
    const float* wm = wts + OFF_WM;
    int o = blockIdx.x, j = threadIdx.x;

    // left half: copy W1x (already tf32)
    wcat[o * 512 + j] = w1[o * 512 + j];

    // right half: (W1m @ Wm)[o][j]
    float acc = 0.f;
    const float* w1m = w1 + o * 512 + 256;
    #pragma unroll 8
    for (int kk = 0; kk < 256; kk++)
        acc = fmaf(w1m[kk], wm[kk * 256 + j], acc);
    wcat[o * 512 + 256 + j] = rtf(acc);

    if (j == 0) {
        float b = b1[o];
        for (int kk = 0; kk < 256; kk++) b = fmaf(w1m[kk], bm[kk], b);
        bf[o] = b;
    }
}

// ---------------------------------------------------------------------------
// bf16 flash attention, P register-resident, S-mma 16-way interleaved.
// grid (N/128, H, B), 128 threads (4 warps), 32 q-rows/warp.
// ---------------------------------------------------------------------------
#define LDB 72          // bf16 pitch for K / V / Q tiles
#define LDT 132         // fp32 pitch for O^T staging

__global__ void __launch_bounds__(128)
flash_attn_bf(const __nv_bfloat16* __restrict__ q, const __nv_bfloat16* __restrict__ k,
              const __nv_bfloat16* __restrict__ v, float* __restrict__ attn,
              int N, int M)
{
    extern __shared__ char smb[];
    __nv_bfloat16* Ks = reinterpret_cast<__nv_bfloat16*>(smb);            // [2][64][LDB]
    __nv_bfloat16* Vs = reinterpret_cast<__nv_bfloat16*>(smb + 18432);    // [2][64][LDB]
    __nv_bfloat16* Qs = reinterpret_cast<__nv_bfloat16*>(smb + 36864);    // [128][LDB]
    float* OT = reinterpret_cast<float*>(smb);                            // [64][LDT]

    const int b  = blockIdx.z, h = blockIdx.y;
    const int n0 = blockIdx.x * 128;
    const int bh = b * HH + h;
    const int t  = threadIdx.x;
    const int wid = t >> 5, lane = t & 31;
    const int g = lane >> 2, tg = lane & 3;
    const int wr = wid * 32;

    const __nv_bfloat16* Kg = k + (size_t)bh * M * 64;
    const __nv_bfloat16* Vg = v + (size_t)bh * 64 * M;

    // prefetch K/V tile 0
    {
        uint32_t kd = smem_u32(Ks), vd = smem_u32(Vs);
        #pragma unroll
        for (int i = 0; i < 4; i++) {
            int idx = t + i * 128;
            int r = idx >> 3, c = (idx & 7) * 8;
            cp16(kd + (uint32_t)(r * LDB + c) * 2, Kg + r * 64 + c);
            cp16(vd + (uint32_t)(r * LDB + c) * 2, Vg + (size_t)r * M + c);
        }
        CP_COMMIT();
    }

    // stage Q
    {
        const __nv_bfloat16* Qg = q + ((size_t)bh * N + n0) * 64;
        #pragma unroll
        for (int i = 0; i < 8; i++) {
            int idx = t + i * 128;
            int r = idx >> 3, c = (idx & 7) * 8;
            *reinterpret_cast<uint4*>(Qs + r * LDB + c) =
                *reinterpret_cast<const uint4*>(Qg + r * 64 + c);
        }
    }
    __syncthreads();

    // persistent Q fragments
    uint32_t Qf[2][4][4];
    #pragma unroll
    for (int mt = 0; mt < 2; mt++) {
        int r0 = wr + mt * 16 + g;
        #pragma unroll
        for (int kk = 0; kk < 4; kk++) {
            Qf[mt][kk][0] = *reinterpret_cast<uint32_t*>(Qs + (r0    ) * LDB + kk * 16 + 2 * tg);
            Qf[mt][kk][1] = *reinterpret_cast<uint32_t*>(Qs + (r0 + 8) * LDB + kk * 16 + 2 * tg);
            Qf[mt][kk][2] = *reinterpret_cast<uint32_t*>(Qs + (r0    ) * LDB + kk * 16 + 2 * tg + 8);
            Qf[mt][kk][3] = *reinterpret_cast<uint32_t*>(Qs + (r0 + 8) * LDB + kk * 16 + 2 * tg + 8);
        }
    }
    __syncthreads();

    float Of[8][2][4] = {};
    float lrow[2][2]  = {};

    const int nT = M / 64;
    for (int tt = 0; tt < nT; tt++) {
        const __nv_bfloat16* Kc = Ks + (tt & 1) * 64 * LDB;
        const __nv_bfloat16* Vc = Vs + (tt & 1) * 64 * LDB;

        if (tt + 1 < nT) {
            uint32_t kd = smem_u32(Ks + ((tt + 1) & 1) * 64 * LDB);
            uint32_t vd = smem_u32(Vs + ((tt + 1) & 1) * 64 * LDB);
            const __nv_bfloat16* Kn = Kg + (size_t)(tt + 1) * 64 * 64;
            const __nv_bfloat16* Vn = Vg + (size_t)(tt + 1) * 64;
            #pragma unroll
            for (int i = 0; i < 4; i++) {
                int idx = t + i * 128;
                int r = idx >> 3, c = (idx & 7) * 8;
                cp16(kd + (uint32_t)(r * LDB + c) * 2, Kn + r * 64 + c);
                cp16(vd + (uint32_t)(r * LDB + c) * 2, Vn + (size_t)r * M + c);
            }
            CP_COMMIT();
            CP_WAIT(1);
        } else {
            CP_WAIT(0);
        }
        __syncthreads();

        // S = Q K^T  — kk OUTER so 16 independent mma fill the latency window
        float Sc[8][2][4] = {};
        #pragma unroll
        for (int kk = 0; kk < 4; kk++) {
            #pragma unroll
            for (int j = 0; j < 8; j++) {
                const __nv_bfloat16* Kr = Kc + (j * 8 + g) * LDB + kk * 16 + 2 * tg;
                uint32_t b0 = *reinterpret_cast<const uint32_t*>(Kr);
                uint32_t b1 = *reinterpret_cast<const uint32_t*>(Kr + 8);
                mma16(Sc[j][0], Qf[0][kk], b0, b1);
                mma16(Sc[j][1], Qf[1][kk], b0, b1);
            }
        }

        // exp2 + row-sum + pack straight into PV A-fragments
        uint32_t Pa[4][2][4];
        #pragma unroll
        for (int mt = 0; mt < 2; mt++) {
            #pragma unroll
            for (int j = 0; j < 8; j++) {
                float e0 = ex2(Sc[j][mt][0]);
                float e1 = ex2(Sc[j][mt][1]);
                float e2 = ex2(Sc[j][mt][2]);
                float e3 = ex2(Sc[j][mt][3]);
                lrow[mt][0] += e0 + e1;
                lrow[mt][1] += e2 + e3;
                int kk = j >> 1, hf = (j & 1) * 2;
                Pa[kk][mt][hf    ] = packbf(e0, e1);
                Pa[kk][mt][hf + 1] = packbf(e2, e3);
            }
        }

        // O += P V  (kk outer, j inner: 16 independent mma)
        #pragma unroll
        for (int kk = 0; kk < 4; kk++) {
            #pragma unroll
            for (int j = 0; j < 8; j++) {
                const __nv_bfloat16* Vr = Vc + (j * 8 + g) * LDB + kk * 16 + 2 * tg;
                uint32_t b0 = *reinterpret_cast<const uint32_t*>(Vr);
                uint32_t b1 = *reinterpret_cast<const uint32_t*>(Vr + 8);
                mma16(Of[j][0], Pa[kk][0], b0, b1);
                mma16(Of[j][1], Pa[kk][1], b0, b1);
            }
        }
        __syncthreads();
    }

    // finalize l
    #pragma unroll
    for (int mt = 0; mt < 2; mt++)
        #pragma unroll
        for (int r = 0; r < 2; r++) {
            float s = lrow[mt][r];
            s += __shfl_xor_sync(0xffffffffu, s, 1);
            s += __shfl_xor_sync(0xffffffffu, s, 2);
            lrow[mt][r] = 1.0f / s;
        }

    __syncthreads();
    #pragma unroll
    for (int j = 0; j < 8; j++) {
        #pragma unroll
        for (int mt = 0; mt < 2; mt++) {
            int r0 = wr + mt * 16 + g;
            OT[(j * 8 + 2 * tg    ) * LDT + r0    ] = Of[j][mt][0] * lrow[mt][0];
            OT[(j * 8 + 2 * tg + 1) * LDT + r0    ] = Of[j][mt][1] * lrow[mt][0];
            OT[(j * 8 + 2 * tg    ) * LDT + r0 + 8] = Of[j][mt][2] * lrow[mt][1];
            OT[(j * 8 + 2 * tg + 1) * LDT + r0 + 8] = Of[j][mt][3] * lrow[mt][1];
        }
    }
    __syncthreads();

    // coalesced tf32-rounded store into (B, D, N), channel = di*H + h
    #pragma unroll
    for (int cc = 0; cc < 16; cc++) {
        int di = wid * 16 + cc;
        float4 val = *reinterpret_cast<const float4*>(OT + di * LDT + lane * 4);
        val.x = rtf(val.x); val.y = rtf(val.y); val.z = rtf(val.z); val.w = rtf(val.w);
        *reinterpret_cast<float4*>(
            attn + ((size_t)(b * DD + di * HH + h)) * N + n0 + lane * 4) = val;
    }
}

// ---------------------------------------------------------------------------
// tf32 GEMM body, tile 128(o) x 128(n), BK=32, double-buffered cp.async.
// 8 warps = 2(o) x 4(n); warp tile 64x32. All fragment loads raw-bit.
// ---------------------------------------------------------------------------
#define LDWM 36
#define LDXM 136

struct GemmOut {
    float acc[4][4][4];
    int o0, n0, wo, wn, g, tg;
};

__device__ __forceinline__ void gemm_body(
    const float* __restrict__ W, const float* __restrict__ X0, int C0,
    const float* __restrict__ X1, int b, int IC, int N,
    int o0, int n0, float* sm, GemmOut& R)
{
    float* Ws = sm;                       // [2][128][LDWM]
    float* Xs = sm + 2 * 128 * LDWM;      // [2][32][LDXM]

    const int t  = threadIdx.x;
    const int wid = t >> 5, lane = t & 31;
    R.g = lane >> 2; R.tg = lane & 3;
    R.wo = (wid & 1) * 64;
    R.wn = (wid >> 1) * 32;
    R.o0 = o0; R.n0 = n0;

    auto stage = [&](int buf, int k0) {
        uint32_t wd = smem_u32(Ws + buf * 128 * LDWM);
        uint32_t xd = smem_u32(Xs + buf * 32 * LDXM);
        #pragma unroll
        for (int i = 0; i < 4; i++) {
            int idx = t + i * 256;
            int r = idx >> 3, c = (idx & 7) * 4;
            cp16(wd + (uint32_t)(r * LDWM + c) * 4,
                 W + (size_t)(o0 + r) * IC + k0 + c);
        }
        #pragma unroll
        for (int i = 0; i < 4; i++) {
            int idx = t + i * 256;
            int r = idx >> 5, c = (idx & 31) * 4;
            int ch = k0 + r;
            const float* src = (ch < C0)
                ? (X0 + ((size_t)b * C0 + ch) * N)
                : (X1 + ((size_t)b * (IC - C0) + (ch - C0)) * N);
            cp16(xd + (uint32_t)(r * LDXM + c) * 4, src + n0 + c);
        }
        CP_COMMIT();
    };

    stage(0, 0);
    #pragma unroll
    for (int a = 0; a < 4; a++)
        #pragma unroll
        for (int c = 0; c < 4; c++)
            #pragma unroll
            for (int d = 0; d < 4; d++) R.acc[a][c][d] = 0.f;

    const int nK = IC / 32;
    for (int kt = 0; kt < nK; kt++) {
        if (kt + 1 < nK) { stage((kt + 1) & 1, (kt + 1) * 32); CP_WAIT(1); }
        else             { CP_WAIT(0); }
        __syncthreads();
        const float* Wc = Ws + (kt & 1) * 128 * LDWM;
        const float* Xc = Xs + (kt & 1) * 32 * LDXM;

        #pragma unroll
        for (int ks = 0; ks < 4; ks++) {
            uint32_t Af[4][4];
            #pragma unroll
            for (int mt = 0; mt < 4; mt++) {
                int r0 = R.wo + mt * 16 + R.g;
                Af[mt][0] = __float_as_uint(Wc[(r0    ) * LDWM + ks * 8 + R.tg]);
                Af[mt][1] = __float_as_uint(Wc[(r0 + 8) * LDWM + ks * 8 + R.tg]);
                Af[mt][2] = __float_as_uint(Wc[(r0    ) * LDWM + ks * 8 + R.tg + 4]);
                Af[mt][3] = __float_as_uint(Wc[(r0 + 8) * LDWM + ks * 8 + R.tg + 4]);
            }
            #pragma unroll
            for (int nt = 0; nt < 4; nt++) {
                uint32_t b0 = __float_as_uint(Xc[(ks * 8 + R.tg    ) * LDXM + R.wn + nt * 8 + R.g]);
                uint32_t b1 = __float_as_uint(Xc[(ks * 8 + R.tg + 4) * LDXM + R.wn + nt * 8 + R.g]);
                #pragma unroll
                for (int mt = 0; mt < 4; mt++)
                    mma8(R.acc[mt][nt], Af[mt], b0, b1);
            }
        }
        __syncthreads();
    }
}

// generic projection: (B,OC,N) layout
__global__ void __launch_bounds__(256)
gemm_tc(const float* __restrict__ W, const float* __restrict__ bias,
        const float* __restrict__ X0, int C0, const float* __restrict__ X1,
        float* __restrict__ out, int OC, int IC, int N, int round_out)
{
    extern __shared__ float sm[];
    GemmOut R;
    gemm_body(W, X0, C0, X1, blockIdx.z, IC, N,
              blockIdx.y * 128, blockIdx.x * 128, sm, R);

    #pragma unroll
    for (int mt = 0; mt < 4; mt++) {
        int o_g  = R.o0 + R.wo + mt * 16 + R.g;
        int o_g8 = o_g + 8;
        float bg  = bias[o_g];
        float bg8 = bias[o_g8];
        #pragma unroll
        for (int nt = 0; nt < 4; nt++) {
            int n = R.n0 + R.wn + nt * 8 + 2 * R.tg;
            float c0 = R.acc[mt][nt][0] + bg,  c1 = R.acc[mt][nt][1] + bg;
            float c2 = R.acc[mt][nt][2] + bg8, c3 = R.acc[mt][nt][3] + bg8;
            if (round_out) { c0 = rtf(c0); c1 = rtf(c1); c2 = rtf(c2); c3 = rtf(c3); }
            *reinterpret_cast<float2*>(out + ((size_t)blockIdx.z * OC + o_g ) * N + n) =
                make_float2(c0, c1);
            *reinterpret_cast<float2*>(out + ((size_t)blockIdx.z * OC + o_g8) * N + n) =
                make_float2(c2, c3);
        }
    }
}

// fused Q/K/V projection: grid (N/128, D/128, 6); z = which*2 + b.
__global__ void __launch_bounds__(256)
gemm_qkv(const float* __restrict__ wts,
         const float* __restrict__ bq, const float* __restrict__ bk,
         const float* __restrict__ bv,
         const float* __restrict__ x, const float* __restrict__ src,
         __nv_bfloat16* __restrict__ qp, __nv_bfloat16* __restrict__ kp,
         __nv_bfloat16* __restrict__ vp, int N)
{
    extern __shared__ float sm[];
    const int z = blockIdx.z;
    const int which = z >> 1;
    const int b = z & 1;
    const float* W    = wts + which * 65536;
    const float* bias = (which == 0) ? bq : (which == 1) ? bk : bv;
    const float* X    = (which == 0) ? x : src;
    const float oscale = (which == 0) ? QSCALE : 1.0f;

    GemmOut R;
    gemm_body(W, X, DD, nullptr, b, DD, N, blockIdx.y * 128, blockIdx.x * 128, sm, R);

    #pragma unroll
    for (int mt = 0; mt < 4; mt++) {
        int o_g  = R.o0 + R.wo + mt * 16 + R.g;
        int o_g8 = o_g + 8;
        float bg  = bias[o_g];
        float bg8 = bias[o_g8];
        #pragma unroll
        for (int nt = 0; nt < 4; nt++) {
            int n = R.n0 + R.wn + nt * 8 + 2 * R.tg;
            float c0 = (R.acc[mt][nt][0] + bg)  * oscale;
            float c1 = (R.acc[mt][nt][1] + bg)  * oscale;
            float c2 = (R.acc[mt][nt][2] + bg8) * oscale;
            float c3 = (R.acc[mt][nt][3] + bg8) * oscale;
            int h0 = o_g & 3,  d0 = o_g >> 2;
            int h1 = o_g8 & 3, d1 = o_g8 >> 2;
            if (which < 2) {
                __nv_bfloat16* out = (which == 0) ? qp : kp;
                out[(((size_t)b * HH + h0) * N + n    ) * 64 + d0] = __float2bfloat16_rn(c0);
                out[(((size_t)b * HH + h0) * N + n + 1) * 64 + d0] = __float2bfloat16_rn(c1);
                out[(((size_t)b * HH + h1) * N + n    ) * 64 + d1] = __float2bfloat16_rn(c2);
                out[(((size_t)b * HH + h1) * N + n + 1) * 64 + d1] = __float2bfloat16_rn(c3);
            } else {
                *reinterpret_cast<uint32_t*>(
                    vp + (((size_t)b * HH + h0) * 64 + d0) * N + n) = packbf(c0, c1);
                *reinterpret_cast<uint32_t*>(
                    vp + (((size_t)b * HH + h1) * 64 + d1) * N + n) = packbf(c2, c3);
            }
        }
    }
}

// ---------------------------------------------------------------------------
// InstanceNorm1d (affine=False, biased var) + ReLU, in place, tf32-rounded out.
// ---------------------------------------------------------------------------
__global__ void instnorm_relu(float* __restrict__ hb, int N)
{
    int row = blockIdx.x;
    float* p = hb + (size_t)row * N;

    float s = 0.f, s2 = 0.f;
    for (int i = threadIdx.x * 4; i < N; i += blockDim.x * 4) {
        float4 v = *reinterpret_cast<const float4*>(p + i);
        s  += (v.x + v.y) + (v.z + v.w);
        s2 += v.x * v.x + v.y * v.y + v.z * v.z + v.w * v.w;
    }
    #pragma unroll
    for (int off = 16; off > 0; off >>= 1) {
        s  += __shfl_xor_sync(0xffffffffu, s,  off);
        s2 += __shfl_xor_sync(0xffffffffu, s2, off);
    }
    __shared__ float sh[16];
    int wid = threadIdx.x >> 5, lid = threadIdx.x & 31;
    if (lid == 0) { sh[wid] = s; sh[wid + 8] = s2; }
    __syncthreads();
    if (threadIdx.x < 32) {
        s  = (lid < 8) ? sh[lid]     : 0.f;
        s2 = (lid < 8) ? sh[lid + 8] : 0.f;
        #pragma unroll
        for (int off = 4; off > 0; off >>= 1) {
            s  += __shfl_xor_sync(0xffffffffu, s,  off);
            s2 += __shfl_xor_sync(0xffffffffu, s2, off);
        }
        if (lid == 0) { sh[0] = s; sh[1] = s2; }
    }
    __syncthreads();
    float mean = sh[0] / (float)N;
    float var  = sh[1] / (float)N - mean * mean;
    float inv  = rsqrtf(var + 1e-5f);
    for (int i = threadIdx.x * 4; i < N; i += blockDim.x * 4) {
        float4 v = *reinterpret_cast<const float4*>(p + i);
        v.x = rtf(fmaxf(0.f, (v.x - mean) * inv));
        v.y = rtf(fmaxf(0.f, (v.y - mean) * inv));
        v.z = rtf(fmaxf(0.f, (v.z - mean) * inv));
        v.w = rtf(fmaxf(0.f, (v.w - mean) * inv));
        *reinterpret_cast<float4*>(p + i) = v;
    }
}

// ---------------------------------------------------------------------------
extern "C" void kernel_launch(void* const* d_in, const int* in_sizes, int n_in,
                              void* d_out, int out_size)
{
    const float* x   = (const float*)d_in[0];
    const float* src = (const float*)d_in[1];
    const float* Wq  = (const float*)d_in[2];
    const float* bq  = (const float*)d_in[3];
    const float* Wk  = (const float*)d_in[4];
    const float* bk  = (const float*)d_in[5];
    const float* Wv  = (const float*)d_in[6];
    const float* bv  = (const float*)d_in[7];
    const float* Wm  = (const float*)d_in[8];
    const float* bm  = (const float*)d_in[9];
    const float* W1  = (const float*)d_in[10];
    const float* b1  = (const float*)d_in[11];
    const float* W2  = (const float*)d_in[12];
    const float* b2  = (const float*)d_in[13];

    const int B = BB, D = DD;
    const int N = in_sizes[0] / (B * D);
    const int M = in_sizes[1] / (B * D);

    __nv_bfloat16 *qp, *kp, *vp;
    float *attnp, *hp, *wts, *xr, *sr, *wcat, *bf;
    cudaGetSymbolAddress((void**)&qp,    g_q);
    cudaGetSymbolAddress((void**)&kp,    g_k);
    cudaGetSymbolAddress((void**)&vp,    g_v);
    cudaGetSymbolAddress((void**)&attnp, g_attn);
    cudaGetSymbolAddress((void**)&hp,    g_h);
    cudaGetSymbolAddress((void**)&wts,   g_wts);
    cudaGetSymbolAddress((void**)&xr,    g_xr);
    cudaGetSymbolAddress((void**)&sr,    g_sr);
    cudaGetSymbolAddress((void**)&wcat,  g_wcat);
    cudaGetSymbolAddress((void**)&bf,    g_bf);

    const int gsmem = (2 * 128 * LDWM + 2 * 32 * LDXM) * (int)sizeof(float);  // 71680
    const int fsmem = 36864 + 128 * LDB * 2;                                   // 55296
    cudaFuncSetAttribute(gemm_tc,  cudaFuncAttributeMaxDynamicSharedMemorySize, gsmem);
    cudaFuncSetAttribute(gemm_qkv, cudaFuncAttributeMaxDynamicSharedMemorySize, gsmem);
    cudaFuncSetAttribute(flash_attn_bf, cudaFuncAttributeMaxDynamicSharedMemorySize, fsmem);

    // 0. producer-side tf32 rounding + message-fold precompute
    round_weights<<<(655360 + 255) / 256, 256>>>(Wq, Wk, Wv, Wm, W1, W2, wts);
    const int nIn = B * D * N;
    round_inputs<<<(nIn / 4 + 255) / 256, 256>>>(x, src, xr, sr, nIn);
    fuse_w1<<<512, 256>>>(wts, b1, bm, wcat, bf);

    // 1. fused Q/K/V projections (bf16; Q pre-scaled; V transposed)
    gemm_qkv<<<dim3(N / 128, D / 128, 3 * B), 256, gsmem>>>(
        wts, bq, bk, bv, xr, sr, qp, kp, vp, N);

    // 2. fused bf16 flash attention
    flash_attn_bf<<<dim3(N / 128, HH, B), 128, fsmem>>>(qp, kp, vp, attnp, N, M);

    // 3+4. fused W1 layer: h = W1x@x + (W1m@Wm)@attn + bf   (virtual concat)
    gemm_tc<<<dim3(N / 128, (2 * D) / 128, B), 256, gsmem>>>(
        wcat, bf, xr, D, attnp, hp, 2 * D, 2 * D, N, 0);

    // 5. InstanceNorm + ReLU (tf32-rounded out)
    instnorm_relu<<<B * 2 * D, 256>>>(hp, N);

    // 6. final projection -> d_out
    gemm_tc<<<dim3(N / 128, D / 128, B), 256, gsmem>>>(
        wts + OFF_W2, b2, hp, 2 * D, nullptr, (float*)d_out, D, 2 * D, N, 0);
}

// round 9
// speedup vs baseline: 1.0905x; 1.0460x over previous
#include <cuda_runtime.h>
#include <cuda_fp16.h>
#include <cuda_bf16.h>
#include <cstdint>
#include <cstddef>

// ---------------------------------------------------------------------------
// AttentionalPropagation, B=2, D=256, H=4, dim=64, N=M=4096.
// R9: flash in fp16 with ex2.approx.f16x2 (half the MUFU work) and a
//     tensor-computed row-sum (ones column in V^T). W1-fold retained.
// ---------------------------------------------------------------------------

#define BB 2
#define DD 256
#define HH 4

__device__ __half g_q[BB * HH * 4096 * 64];   // [b][h][n][di], pre-scaled
__device__ __half g_k[BB * HH * 4096 * 64];   // [b][h][m][di]
__device__ __half g_v[BB * HH * 64 * 4096];   // [b][h][di][m] (transposed)
__device__ float g_attn[BB * DD * 4096];      // (B, D, N), tf32-rounded
__device__ float g_h   [BB * 2 * DD * 4096];  // (B, 2D, N)
__device__ float g_wts [655360];              // tf32-rounded weights
__device__ float g_xr  [BB * DD * 4096];      // tf32-rounded x
__device__ float g_sr  [BB * DD * 4096];      // tf32-rounded source
__device__ float g_wcat[512 * 512];           // [W1x | W1m@Wm], tf32
__device__ float g_bf  [512];                 // W1m@bm + b1

#define OFF_WQ 0
#define OFF_WK 65536
#define OFF_WV 131072
#define OFF_WM 196608
#define OFF_W1 262144
#define OFF_W2 524288

#define QSCALE (0.125f * 1.44269504088896340736f)   // 1/sqrt(64) * log2(e)

// ============================ PTX helpers ==================================
__device__ __forceinline__ uint32_t smem_u32(const void* p) {
    uint32_t a;
    asm("{ .reg .u64 t; cvta.to.shared.u64 t, %1; cvt.u32.u64 %0, t; }"
        : "=r"(a) : "l"(p));
    return a;
}
__device__ __forceinline__ uint32_t f2tf(float x) {
    uint32_t r; asm("cvt.rna.tf32.f32 %0, %1;" : "=r"(r) : "f"(x)); return r;
}
__device__ __forceinline__ float rtf(float x) { return __uint_as_float(f2tf(x)); }
__device__ __forceinline__ uint32_t packh(float lo, float hi) {
    __half2 h = __floats2half2_rn(lo, hi);
    return *reinterpret_cast<uint32_t*>(&h);
}
__device__ __forceinline__ uint32_t ex2h2(uint32_t h2) {
    uint32_t r; asm("ex2.approx.f16x2 %0, %1;" : "=r"(r) : "r"(h2)); return r;
}
// tf32 m16n8k8
__device__ __forceinline__ void mma8(float* d, const uint32_t* a,
                                     uint32_t b0, uint32_t b1) {
    asm volatile("mma.sync.aligned.m16n8k8.row.col.f32.tf32.tf32.f32 "
        "{%0,%1,%2,%3}, {%4,%5,%6,%7}, {%8,%9}, {%0,%1,%2,%3};"
        : "+f"(d[0]), "+f"(d[1]), "+f"(d[2]), "+f"(d[3])
        : "r"(a[0]), "r"(a[1]), "r"(a[2]), "r"(a[3]), "r"(b0), "r"(b1));
}
// fp16 m16n8k16
__device__ __forceinline__ void mma16f(float* d, const uint32_t* a,
                                       uint32_t b0, uint32_t b1) {
    asm volatile("mma.sync.aligned.m16n8k16.row.col.f32.f16.f16.f32 "
        "{%0,%1,%2,%3}, {%4,%5,%6,%7}, {%8,%9}, {%0,%1,%2,%3};"
        : "+f"(d[0]), "+f"(d[1]), "+f"(d[2]), "+f"(d[3])
        : "r"(a[0]), "r"(a[1]), "r"(a[2]), "r"(a[3]), "r"(b0), "r"(b1));
}
__device__ __forceinline__ void cp16(uint32_t s, const void* g) {
    asm volatile("cp.async.ca.shared.global [%0], [%1], 16;" :: "r"(s), "l"(g));
}
#define CP_COMMIT() asm volatile("cp.async.commit_group;" ::: "memory")
#define CP_WAIT(n)  asm volatile("cp.async.wait_group %0;" :: "n"(n) : "memory")

// ---------------------------------------------------------------------------
// producer rounding kernels (deterministic)
// ---------------------------------------------------------------------------
__global__ void round_weights(const float* __restrict__ wq, const float* __restrict__ wk,
                              const float* __restrict__ wv, const float* __restrict__ wm,
                              const float* __restrict__ w1, const float* __restrict__ w2,
                              float* __restrict__ dst)
{
    int i = blockIdx.x * 256 + threadIdx.x;
    if (i >= 655360) return;
    float v;
    if      (i < OFF_WK) v = wq[i - OFF_WQ];
    else if (i < OFF_WV) v = wk[i - OFF_WK];
    else if (i < OFF_WM) v = wv[i - OFF_WV];
    else if (i < OFF_W1) v = wm[i - OFF_WM];
    else if (i < OFF_W2) v = w1[i - OFF_W1];
    else                 v = w2[i - OFF_W2];
    dst[i] = rtf(v);
}

__global__ void round_inputs(const float* __restrict__ x, const float* __restrict__ src,
                             float* __restrict__ xr, float* __restrict__ sr, int n)
{
    int i = (blockIdx.x * 256 + threadIdx.x) * 4;
    if (i >= n) return;
    float4 a = *reinterpret_cast<const float4*>(x + i);
    float4 b = *reinterpret_cast<const float4*>(src + i);
    a.x = rtf(a.x); a.y = rtf(a.y); a.z = rtf(a.z); a.w = rtf(a.w);
    b.x = rtf(b.x); b.y = rtf(b.y); b.z = rtf(b.z); b.w = rtf(b.w);
    *reinterpret_cast<float4*>(xr + i) = a;
    *reinterpret_cast<float4*>(sr + i) = b;
}

// ---------------------------------------------------------------------------
// fold message projection: Wcat = [W1x | rtf(W1m @ Wm)], bf = W1m @ bm + b1.
// ---------------------------------------------------------------------------
__global__ void fuse_w1(const float* __restrict__ wts, const float* __restrict__ b1,
                        const float* __restrict__ bm,
                        float* __restrict__ wcat, float* __restrict__ bf)
{
    const float* w1 = wts + OFF_W1;
    const float* wm = wts + OFF_WM;
    int o = blockIdx.x, j = threadIdx.x;

    wcat[o * 512 + j] = w1[o * 512 + j];

    float acc = 0.f;
    const float* w1m = w1 + o * 512 + 256;
    #pragma unroll 8
    for (int kk = 0; kk < 256; kk++)
        acc = fmaf(w1m[kk], wm[kk * 256 + j], acc);
    wcat[o * 512 + 256 + j] = rtf(acc);

    if (j == 0) {
        float b = b1[o];
        for (int kk = 0; kk < 256; kk++) b = fmaf(w1m[kk], bm[kk], b);
        bf[o] = b;
    }
}

// ---------------------------------------------------------------------------
// fp16 flash attention; ex2.f16x2 softmax; tensor-core row sums (ones column).
// grid (N/128, H, B), 128 threads (4 warps), 32 q-rows/warp.
// V^T smem tile has 72 rows: 0-63 data, 64 = ones, 65-71 = zeros.
// ---------------------------------------------------------------------------
#define LDB   72        // fp16 pitch
#define VROWS 72
#define LDT  132        // fp32 pitch for O^T staging

__global__ void __launch_bounds__(128)
flash_attn_fp16(const __half* __restrict__ q, const __half* __restrict__ k,
                const __half* __restrict__ v, float* __restrict__ attn,
                int N, int M)
{
    extern __shared__ char smb[];
    __half* Ks = reinterpret_cast<__half*>(smb);             // [2][64][LDB]
    __half* Vs = reinterpret_cast<__half*>(smb + 18432);     // [2][VROWS][LDB]
    __half* Qs = reinterpret_cast<__half*>(smb + 39168);     // [128][LDB]
    float*  OT = reinterpret_cast<float*>(smb);              // [64][LDT] epilogue

    const int b  = blockIdx.z, h = blockIdx.y;
    const int n0 = blockIdx.x * 128;
    const int bh = b * HH + h;
    const int t  = threadIdx.x;
    const int wid = t >> 5, lane = t & 31;
    const int g = lane >> 2, tg = lane & 3;
    const int wr = wid * 32;

    const __half* Kg = k + (size_t)bh * M * 64;
    const __half* Vg = v + (size_t)bh * 64 * M;

    // prefetch K/V tile 0 (rows 0..63)
    {
        uint32_t kd = smem_u32(Ks), vd = smem_u32(Vs);
        #pragma unroll
        for (int i = 0; i < 4; i++) {
            int idx = t + i * 128;
            int r = idx >> 3, c = (idx & 7) * 8;
            cp16(kd + (uint32_t)(r * LDB + c) * 2, Kg + r * 64 + c);
            cp16(vd + (uint32_t)(r * LDB + c) * 2, Vg + (size_t)r * M + c);
        }
        CP_COMMIT();
    }

    // init ones/zeros rows 64..71 of both V buffers (outside cp.async region)
    {
        const __half one = __float2half(1.0f);
        const __half zer = __float2half(0.0f);
        for (int i = t; i < 2 * 8 * LDB; i += 128) {
            int buf = i / (8 * LDB);
            int rem = i - buf * 8 * LDB;
            int r = rem / LDB, c = rem - r * LDB;
            Vs[(size_t)buf * VROWS * LDB + (64 + r) * LDB + c] = (r == 0) ? one : zer;
        }
    }

    // stage Q
    {
        const __half* Qg = q + ((size_t)bh * N + n0) * 64;
        #pragma unroll
        for (int i = 0; i < 8; i++) {
            int idx = t + i * 128;
            int r = idx >> 3, c = (idx & 7) * 8;
            *reinterpret_cast<uint4*>(Qs + r * LDB + c) =
                *reinterpret_cast<const uint4*>(Qg + r * 64 + c);
        }
    }
    __syncthreads();

    // persistent Q fragments
    uint32_t Qf[2][4][4];
    #pragma unroll
    for (int mt = 0; mt < 2; mt++) {
        int r0 = wr + mt * 16 + g;
        #pragma unroll
        for (int kk = 0; kk < 4; kk++) {
            Qf[mt][kk][0] = *reinterpret_cast<uint32_t*>(Qs + (r0    ) * LDB + kk * 16 + 2 * tg);
            Qf[mt][kk][1] = *reinterpret_cast<uint32_t*>(Qs + (r0 + 8) * LDB + kk * 16 + 2 * tg);
            Qf[mt][kk][2] = *reinterpret_cast<uint32_t*>(Qs + (r0    ) * LDB + kk * 16 + 2 * tg + 8);
            Qf[mt][kk][3] = *reinterpret_cast<uint32_t*>(Qs + (r0 + 8) * LDB + kk * 16 + 2 * tg + 8);
        }
    }
    __syncthreads();

    float Of[9][2][4] = {};     // Of[8] = l accumulators (cols 64..71)

    const int nT = M / 64;
    for (int tt = 0; tt < nT; tt++) {
        const __half* Kc = Ks + (size_t)(tt & 1) * 64 * LDB;
        const __half* Vc = Vs + (size_t)(tt & 1) * VROWS * LDB;

        if (tt + 1 < nT) {
            uint32_t kd = smem_u32(Ks + (size_t)((tt + 1) & 1) * 64 * LDB);
            uint32_t vd = smem_u32(Vs + (size_t)((tt + 1) & 1) * VROWS * LDB);
            const __half* Kn = Kg + (size_t)(tt + 1) * 64 * 64;
            const __half* Vn = Vg + (size_t)(tt + 1) * 64;
            #pragma unroll
            for (int i = 0; i < 4; i++) {
                int idx = t + i * 128;
                int r = idx >> 3, c = (idx & 7) * 8;
                cp16(kd + (uint32_t)(r * LDB + c) * 2, Kn + r * 64 + c);
                cp16(vd + (uint32_t)(r * LDB + c) * 2, Vn + (size_t)r * M + c);
            }
            CP_COMMIT();
            CP_WAIT(1);
        } else {
            CP_WAIT(0);
        }
        __syncthreads();

        // S = Q K^T  (kk outer: 16 independent mma)
        float Sc[8][2][4] = {};
        #pragma unroll
        for (int kk = 0; kk < 4; kk++) {
            #pragma unroll
            for (int j = 0; j < 8; j++) {
                const __half* Kr = Kc + (j * 8 + g) * LDB + kk * 16 + 2 * tg;
                uint32_t b0 = *reinterpret_cast<const uint32_t*>(Kr);
                uint32_t b1 = *reinterpret_cast<const uint32_t*>(Kr + 8);
                mma16f(Sc[j][0], Qf[0][kk], b0, b1);
                mma16f(Sc[j][1], Qf[1][kk], b0, b1);
            }
        }

        // exp2 in f16x2 — results are the PV A-fragments directly
        uint32_t Pa[4][2][4];
        #pragma unroll
        for (int mt = 0; mt < 2; mt++) {
            #pragma unroll
            for (int j = 0; j < 8; j++) {
                int kk = j >> 1, hf = (j & 1) * 2;
                Pa[kk][mt][hf    ] = ex2h2(packh(Sc[j][mt][0], Sc[j][mt][1]));
                Pa[kk][mt][hf + 1] = ex2h2(packh(Sc[j][mt][2], Sc[j][mt][3]));
            }
        }

        // O += P V ; j=8 block accumulates l into Of[8] via ones column
        #pragma unroll
        for (int kk = 0; kk < 4; kk++) {
            #pragma unroll
            for (int j = 0; j < 9; j++) {
                const __half* Vr = Vc + (j * 8 + g) * LDB + kk * 16 + 2 * tg;
                uint32_t b0 = *reinterpret_cast<const uint32_t*>(Vr);
                uint32_t b1 = *reinterpret_cast<const uint32_t*>(Vr + 8);
                mma16f(Of[j][0], Pa[kk][0], b0, b1);
                mma16f(Of[j][1], Pa[kk][1], b0, b1);
            }
        }
        __syncthreads();
    }

    // l lives in col 64 -> tg==0 threads (Of[8][mt][0]=row g, [2]=row g+8)
    float linv[2][2];
    #pragma unroll
    for (int mt = 0; mt < 2; mt++) {
        float l0 = __shfl_sync(0xffffffffu, Of[8][mt][0], lane & ~3);
        float l1 = __shfl_sync(0xffffffffu, Of[8][mt][2], lane & ~3);
        linv[mt][0] = 1.0f / l0;
        linv[mt][1] = 1.0f / l1;
    }

    __syncthreads();   // K/V smem dead; reuse as OT
    #pragma unroll
    for (int j = 0; j < 8; j++) {
        #pragma unroll
        for (int mt = 0; mt < 2; mt++) {
            int r0 = wr + mt * 16 + g;
            OT[(j * 8 + 2 * tg    ) * LDT + r0    ] = Of[j][mt][0] * linv[mt][0];
            OT[(j * 8 + 2 * tg + 1) * LDT + r0    ] = Of[j][mt][1] * linv[mt][0];
            OT[(j * 8 + 2 * tg    ) * LDT + r0 + 8] = Of[j][mt][2] * linv[mt][1];
            OT[(j * 8 + 2 * tg + 1) * LDT + r0 + 8] = Of[j][mt][3] * linv[mt][1];
        }
    }
    __syncthreads();

    // coalesced tf32-rounded store into (B, D, N), channel = di*H + h
    #pragma unroll
    for (int cc = 0; cc < 16; cc++) {
        int di = wid * 16 + cc;
        float4 val = *reinterpret_cast<const float4*>(OT + di * LDT + lane * 4);
        val.x = rtf(val.x); val.y = rtf(val.y); val.z = rtf(val.z); val.w = rtf(val.w);
        *reinterpret_cast<float4*>(
            attn + ((size_t)(b * DD + di * HH + h)) * N + n0 + lane * 4) = val;
    }
}

// ---------------------------------------------------------------------------
// tf32 GEMM body, tile 128(o) x 128(n), BK=32, double-buffered cp.async.
// 8 warps = 2(o) x 4(n); warp tile 64x32. All fragment loads raw-bit.
// ---------------------------------------------------------------------------
#define LDWM 36
#define LDXM 136

struct GemmOut {
    float acc[4][4][4];
    int o0, n0, wo, wn, g, tg;
};

__device__ __forceinline__ void gemm_body(
    const float* __restrict__ W, const float* __restrict__ X0, int C0,
    const float* __restrict__ X1, int b, int IC, int N,
    int o0, int n0, float* sm, GemmOut& R)
{
    float* Ws = sm;                       // [2][128][LDWM]
    float* Xs = sm + 2 * 128 * LDWM;      // [2][32][LDXM]

    const int t  = threadIdx.x;
    const int wid = t >> 5, lane = t & 31;
    R.g = lane >> 2; R.tg = lane & 3;
    R.wo = (wid & 1) * 64;
    R.wn = (wid >> 1) * 32;
    R.o0 = o0; R.n0 = n0;

    auto stage = [&](int buf, int k0) {
        uint32_t wd = smem_u32(Ws + buf * 128 * LDWM);
        uint32_t xd = smem_u32(Xs + buf * 32 * LDXM);
        #pragma unroll
        for (int i = 0; i < 4; i++) {
            int idx = t + i * 256;
            int r = idx >> 3, c = (idx & 7) * 4;
            cp16(wd + (uint32_t)(r * LDWM + c) * 4,
                 W + (size_t)(o0 + r) * IC + k0 + c);
        }
        #pragma unroll
        for (int i = 0; i < 4; i++) {
            int idx = t + i * 256;
            int r = idx >> 5, c = (idx & 31) * 4;
            int ch = k0 + r;
            const float* src = (ch < C0)
                ? (X0 + ((size_t)b * C0 + ch) * N)
                : (X1 + ((size_t)b * (IC - C0) + (ch - C0)) * N);
            cp16(xd + (uint32_t)(r * LDXM + c) * 4, src + n0 + c);
        }
        CP_COMMIT();
    };

    stage(0, 0);
    #pragma unroll
    for (int a = 0; a < 4; a++)
        #pragma unroll
        for (int c = 0; c < 4; c++)
            #pragma unroll
            for (int d = 0; d < 4; d++) R.acc[a][c][d] = 0.f;

    const int nK = IC / 32;
    for (int kt = 0; kt < nK; kt++) {
        if (kt + 1 < nK) { stage((kt + 1) & 1, (kt + 1) * 32); CP_WAIT(1); }
        else             { CP_WAIT(0); }
        __syncthreads();
        const float* Wc = Ws + (kt & 1) * 128 * LDWM;
        const float* Xc = Xs + (kt & 1) * 32 * LDXM;

        #pragma unroll
        for (int ks = 0; ks < 4; ks++) {
            uint32_t Af[4][4];
            #pragma unroll
            for (int mt = 0; mt < 4; mt++) {
                int r0 = R.wo + mt * 16 + R.g;
                Af[mt][0] = __float_as_uint(Wc[(r0    ) * LDWM + ks * 8 + R.tg]);
                Af[mt][1] = __float_as_uint(Wc[(r0 + 8) * LDWM + ks * 8 + R.tg]);
                Af[mt][2] = __float_as_uint(Wc[(r0    ) * LDWM + ks * 8 + R.tg + 4]);
                Af[mt][3] = __float_as_uint(Wc[(r0 + 8) * LDWM + ks * 8 + R.tg + 4]);
            }
            #pragma unroll
            for (int nt = 0; nt < 4; nt++) {
                uint32_t b0 = __float_as_uint(Xc[(ks * 8 + R.tg    ) * LDXM + R.wn + nt * 8 + R.g]);
                uint32_t b1 = __float_as_uint(Xc[(ks * 8 + R.tg + 4) * LDXM + R.wn + nt * 8 + R.g]);
                #pragma unroll
                for (int mt = 0; mt < 4; mt++)
                    mma8(R.acc[mt][nt], Af[mt], b0, b1);
            }
        }
        __syncthreads();
    }
}

// generic projection: (B,OC,N) layout
__global__ void __launch_bounds__(256)
gemm_tc(const float* __restrict__ W, const float* __restrict__ bias,
        const float* __restrict__ X0, int C0, const float* __restrict__ X1,
        float* __restrict__ out, int OC, int IC, int N, int round_out)
{
    extern __shared__ float sm[];
    GemmOut R;
    gemm_body(W, X0, C0, X1, blockIdx.z, IC, N,
              blockIdx.y * 128, blockIdx.x * 128, sm, R);

    #pragma unroll
    for (int mt = 0; mt < 4; mt++) {
        int o_g  = R.o0 + R.wo + mt * 16 + R.g;
        int o_g8 = o_g + 8;
        float bg  = bias[o_g];
        float bg8 = bias[o_g8];
        #pragma unroll
        for (int nt = 0; nt < 4; nt++) {
            int n = R.n0 + R.wn + nt * 8 + 2 * R.tg;
            float c0 = R.acc[mt][nt][0] + bg,  c1 = R.acc[mt][nt][1] + bg;
            float c2 = R.acc[mt][nt][2] + bg8, c3 = R.acc[mt][nt][3] + bg8;
            if (round_out) { c0 = rtf(c0); c1 = rtf(c1); c2 = rtf(c2); c3 = rtf(c3); }
            *reinterpret_cast<float2*>(out + ((size_t)blockIdx.z * OC + o_g ) * N + n) =
                make_float2(c0, c1);
            *reinterpret_cast<float2*>(out + ((size_t)blockIdx.z * OC + o_g8) * N + n) =
                make_float2(c2, c3);
        }
    }
}

// fused Q/K/V projection: grid (N/128, D/128, 6); z = which*2 + b.
__global__ void __launch_bounds__(256)
gemm_qkv(const float* __restrict__ wts,
         const float* __restrict__ bq, const float* __restrict__ bk,
         const float* __restrict__ bv,
         const float* __restrict__ x, const float* __restrict__ src,
         __half* __restrict__ qp, __half* __restrict__ kp,
         __half* __restrict__ vp, int N)
{
    extern __shared__ float sm[];
    const int z = blockIdx.z;
    const int which = z >> 1;
    const int b = z & 1;
    const float* W    = wts + which * 65536;
    const float* bias = (which == 0) ? bq : (which == 1) ? bk : bv;
    const float* X    = (which == 0) ? x : src;
    const float oscale = (which == 0) ? QSCALE : 1.0f;

    GemmOut R;
    gemm_body(W, X, DD, nullptr, b, DD, N, blockIdx.y * 128, blockIdx.x * 128, sm, R);

    #pragma unroll
    for (int mt = 0; mt < 4; mt++) {
        int o_g  = R.o0 + R.wo + mt * 16 + R.g;
        int o_g8 = o_g + 8;
        float bg  = bias[o_g];
        float bg8 = bias[o_g8];
        #pragma unroll
        for (int nt = 0; nt < 4; nt++) {
            int n = R.n0 + R.wn + nt * 8 + 2 * R.tg;
            float c0 = (R.acc[mt][nt][0] + bg)  * oscale;
            float c1 = (R.acc[mt][nt][1] + bg)  * oscale;
            float c2 = (R.acc[mt][nt][2] + bg8) * oscale;
            float c3 = (R.acc[mt][nt][3] + bg8) * oscale;
            int h0 = o_g & 3,  d0 = o_g >> 2;
            int h1 = o_g8 & 3, d1 = o_g8 >> 2;
            if (which < 2) {
                __half* out = (which == 0) ? qp : kp;
                out[(((size_t)b * HH + h0) * N + n    ) * 64 + d0] = __float2half_rn(c0);
                out[(((size_t)b * HH + h0) * N + n + 1) * 64 + d0] = __float2half_rn(c1);
                out[(((size_t)b * HH + h1) * N + n    ) * 64 + d1] = __float2half_rn(c2);
                out[(((size_t)b * HH + h1) * N + n + 1) * 64 + d1] = __float2half_rn(c3);
            } else {
                *reinterpret_cast<uint32_t*>(
                    vp + (((size_t)b * HH + h0) * 64 + d0) * N + n) = packh(c0, c1);
                *reinterpret_cast<uint32_t*>(
                    vp + (((size_t)b * HH + h1) * 64 + d1) * N + n) = packh(c2, c3);
            }
        }
    }
}

// ---------------------------------------------------------------------------
// InstanceNorm1d (affine=False, biased var) + ReLU, in place, tf32-rounded out.
// ---------------------------------------------------------------------------
__global__ void instnorm_relu(float* __restrict__ hb, int N)
{
    int row = blockIdx.x;
    float* p = hb + (size_t)row * N;

    float s = 0.f, s2 = 0.f;
    for (int i = threadIdx.x * 4; i < N; i += blockDim.x * 4) {
        float4 v = *reinterpret_cast<const float4*>(p + i);
        s  += (v.x + v.y) + (v.z + v.w);
        s2 += v.x * v.x + v.y * v.y + v.z * v.z + v.w * v.w;
    }
    #pragma unroll
    for (int off = 16; off > 0; off >>= 1) {
        s  += __shfl_xor_sync(0xffffffffu, s,  off);
        s2 += __shfl_xor_sync(0xffffffffu, s2, off);
    }
    __shared__ float sh[16];
    int wid = threadIdx.x >> 5, lid = threadIdx.x & 31;
    if (lid == 0) { sh[wid] = s; sh[wid + 8] = s2; }
    __syncthreads();
    if (threadIdx.x < 32) {
        s  = (lid < 8) ? sh[lid]     : 0.f;
        s2 = (lid < 8) ? sh[lid + 8] : 0.f;
        #pragma unroll
        for (int off = 4; off > 0; off >>= 1) {
            s  += __shfl_xor_sync(0xffffffffu, s,  off);
            s2 += __shfl_xor_sync(0xffffffffu, s2, off);
        }
        if (lid == 0) { sh[0] = s; sh[1] = s2; }
    }
    __syncthreads();
    float mean = sh[0] / (float)N;
    float var  = sh[1] / (float)N - mean * mean;
    float inv  = rsqrtf(var + 1e-5f);
    for (int i = threadIdx.x * 4; i < N; i += blockDim.x * 4) {
        float4 v = *reinterpret_cast<const float4*>(p + i);
        v.x = rtf(fmaxf(0.f, (v.x - mean) * inv));
        v.y = rtf(fmaxf(0.f, (v.y - mean) * inv));
        v.z = rtf(fmaxf(0.f, (v.z - mean) * inv));
        v.w = rtf(fmaxf(0.f, (v.w - mean) * inv));
        *reinterpret_cast<float4*>(p + i) = v;
    }
}

// ---------------------------------------------------------------------------
extern "C" void kernel_launch(void* const* d_in, const int* in_sizes, int n_in,
                              void* d_out, int out_size)
{
    const float* x   = (const float*)d_in[0];
    const float* src = (const float*)d_in[1];
    const float* Wq  = (const float*)d_in[2];
    const float* bq  = (const float*)d_in[3];
    const float* Wk  = (const float*)d_in[4];
    const float* bk  = (const float*)d_in[5];
    const float* Wv  = (const float*)d_in[6];
    const float* bv  = (const float*)d_in[7];
    const float* Wm  = (const float*)d_in[8];
    const float* bm  = (const float*)d_in[9];
    const float* W1  = (const float*)d_in[10];
    const float* b1  = (const float*)d_in[11];
    const float* W2  = (const float*)d_in[12];
    const float* b2  = (const float*)d_in[13];

    const int B = BB, D = DD;
    const int N = in_sizes[0] / (B * D);
    const int M = in_sizes[1] / (B * D);

    __half *qp, *kp, *vp;
    float *attnp, *hp, *wts, *xr, *sr, *wcat, *bf;
    cudaGetSymbolAddress((void**)&qp,    g_q);
    cudaGetSymbolAddress((void**)&kp,    g_k);
    cudaGetSymbolAddress((void**)&vp,    g_v);
    cudaGetSymbolAddress((void**)&attnp, g_attn);
    cudaGetSymbolAddress((void**)&hp,    g_h);
    cudaGetSymbolAddress((void**)&wts,   g_wts);
    cudaGetSymbolAddress((void**)&xr,    g_xr);
    cudaGetSymbolAddress((void**)&sr,    g_sr);
    cudaGetSymbolAddress((void**)&wcat,  g_wcat);
    cudaGetSymbolAddress((void**)&bf,    g_bf);

    const int gsmem = (2 * 128 * LDWM + 2 * 32 * LDXM) * (int)sizeof(float);  // 71680
    const int fsmem = 18432 + 20736 + 18432;                                   // 57600
    cudaFuncSetAttribute(gemm_tc,  cudaFuncAttributeMaxDynamicSharedMemorySize, gsmem);
    cudaFuncSetAttribute(gemm_qkv, cudaFuncAttributeMaxDynamicSharedMemorySize, gsmem);
    cudaFuncSetAttribute(flash_attn_fp16, cudaFuncAttributeMaxDynamicSharedMemorySize, fsmem);

    // 0. producer-side tf32 rounding + message-fold precompute
    round_weights<<<(655360 + 255) / 256, 256>>>(Wq, Wk, Wv, Wm, W1, W2, wts);
    const int nIn = B * D * N;
    round_inputs<<<(nIn / 4 + 255) / 256, 256>>>(x, src, xr, sr, nIn);
    fuse_w1<<<512, 256>>>(wts, b1, bm, wcat, bf);

    // 1. fused Q/K/V projections (fp16; Q pre-scaled; V transposed)
    gemm_qkv<<<dim3(N / 128, D / 128, 3 * B), 256, gsmem>>>(
        wts, bq, bk, bv, xr, sr, qp, kp, vp, N);

    // 2. fused fp16 flash attention
    flash_attn_fp16<<<dim3(N / 128, HH, B), 128, fsmem>>>(qp, kp, vp, attnp, N, M);

    // 3+4. fused W1 layer: h = W1x@x + (W1m@Wm)@attn + bf
    gemm_tc<<<dim3(N / 128, (2 * D) / 128, B), 256, gsmem>>>(
        wcat, bf, xr, D, attnp, hp, 2 * D, 2 * D, N, 0);

    // 5. InstanceNorm + ReLU (tf32-rounded out)
    instnorm_relu<<<B * 2 * D, 256>>>(hp, N);

    // 6. final projection -> d_out
    gemm_tc<<<dim3(N / 128, D / 128, B), 256, gsmem>>>(
        wts + OFF_W2, b2, hp, 2 * D, nullptr, (float*)d_out, D, 2 * D, N, 0);
}

// round 10
// speedup vs baseline: 1.2048x; 1.1048x over previous
#include <cuda_runtime.h>
#include <cuda_fp16.h>
#include <cstdint>
#include <cstddef>

// ---------------------------------------------------------------------------
// AttentionalPropagation, B=2, D=256, H=4, dim=64, N=M=4096.
// R10: everything fp16 mma.m16n8k16 (same mantissa as tf32, half the work).
//      Activations stored transposed (B,N,C) fp16 so both GEMM operands have
//      contiguous k-pairs. W1-fold + permuted attn channels retained.
// ---------------------------------------------------------------------------

#define BB 2
#define DD 256
#define HH 4

__device__ __half g_q[BB * HH * 4096 * 64];   // [b][h][n][di], pre-scaled
__device__ __half g_k[BB * HH * 4096 * 64];   // [b][h][m][di]
__device__ __half g_v[BB * HH * 64 * 4096];   // [b][h][di][m] (transposed)
__device__ __half g_xt  [BB * 4096 * DD];     // x  transposed (B,N,256) fp16
__device__ __half g_st  [BB * 4096 * DD];     // src transposed
__device__ __half g_attn[BB * 4096 * DD];     // attn (B,N,256), ch = h*64+di
__device__ __half g_h   [BB * 2 * DD * 4096]; // (B,2D,N) fp16 (pre-norm)
__device__ __half g_ht  [BB * 4096 * 2 * DD]; // (B,N,512) fp16 (post-norm)
__device__ __half g_wts [655360];             // fp16 weights
__device__ __half g_wcat[512 * 512];          // [W1x | perm(W1m@Wm)] fp16
__device__ float  g_bf  [512];                // W1m@bm + b1
__device__ float  g_stats[BB * 2 * DD * 2];   // per (b,c): mean, inv

#define OFF_WQ 0
#define OFF_WK 65536
#define OFF_WV 131072
#define OFF_WM 196608
#define OFF_W1 262144
#define OFF_W2 524288

#define QSCALE (0.125f * 1.44269504088896340736f)   // 1/sqrt(64) * log2(e)

// ============================ PTX helpers ==================================
__device__ __forceinline__ uint32_t smem_u32(const void* p) {
    uint32_t a;
    asm("{ .reg .u64 t; cvta.to.shared.u64 t, %1; cvt.u32.u64 %0, t; }"
        : "=r"(a) : "l"(p));
    return a;
}
__device__ __forceinline__ uint32_t packh(float lo, float hi) {
    __half2 h = __floats2half2_rn(lo, hi);
    return *reinterpret_cast<uint32_t*>(&h);
}
__device__ __forceinline__ uint32_t ex2h2(uint32_t h2) {
    uint32_t r; asm("ex2.approx.f16x2 %0, %1;" : "=r"(r) : "r"(h2)); return r;
}
// fp16 m16n8k16
__device__ __forceinline__ void mma16f(float* d, const uint32_t* a,
                                       uint32_t b0, uint32_t b1) {
    asm volatile("mma.sync.aligned.m16n8k16.row.col.f32.f16.f16.f32 "
        "{%0,%1,%2,%3}, {%4,%5,%6,%7}, {%8,%9}, {%0,%1,%2,%3};"
        : "+f"(d[0]), "+f"(d[1]), "+f"(d[2]), "+f"(d[3])
        : "r"(a[0]), "r"(a[1]), "r"(a[2]), "r"(a[3]), "r"(b0), "r"(b1));
}
__device__ __forceinline__ void cp16(uint32_t s, const void* g) {
    asm volatile("cp.async.ca.shared.global [%0], [%1], 16;" :: "r"(s), "l"(g));
}
#define CP_COMMIT() asm volatile("cp.async.commit_group;" ::: "memory")
#define CP_WAIT(n)  asm volatile("cp.async.wait_group %0;" :: "n"(n) : "memory")

// ---------------------------------------------------------------------------
// producers: weight fp16 conversion, input transpose, W1 fold
// ---------------------------------------------------------------------------
__global__ void round_weights(const float* __restrict__ wq, const float* __restrict__ wk,
                              const float* __restrict__ wv, const float* __restrict__ wm,
                              const float* __restrict__ w1, const float* __restrict__ w2,
                              __half* __restrict__ dst)
{
    int i = blockIdx.x * 256 + threadIdx.x;
    if (i >= 655360) return;
    float v;
    if      (i < OFF_WK) v = wq[i - OFF_WQ];
    else if (i < OFF_WV) v = wk[i - OFF_WK];
    else if (i < OFF_WM) v = wv[i - OFF_WV];
    else if (i < OFF_W1) v = wm[i - OFF_WM];
    else if (i < OFF_W2) v = w1[i - OFF_W1];
    else                 v = w2[i - OFF_W2];
    dst[i] = __float2half_rn(v);
}

// transpose (B,256,N) fp32 -> (B,N,256) fp16, 32x32 smem tiles.
// grid (N/32, 256/32, 4); z: bit0 = b, bit1 = which array.
__global__ void transpose_in(const float* __restrict__ x, const float* __restrict__ src,
                             __half* __restrict__ xt, __half* __restrict__ st, int N)
{
    __shared__ __half tile[32][33];
    const int which = blockIdx.z >> 1, b = blockIdx.z & 1;
    const float* in = which ? src : x;
    __half* out = which ? st : xt;
    const int c0 = blockIdx.y * 32, n0 = blockIdx.x * 32;
    const int tx = threadIdx.x & 31, ty = threadIdx.x >> 5;

    #pragma unroll
    for (int i = 0; i < 4; i++) {
        int c = ty + i * 8;
        tile[c][tx] = __float2half_rn(in[((size_t)(b * DD + c0 + c)) * N + n0 + tx]);
    }
    __syncthreads();
    #pragma unroll
    for (int i = 0; i < 4; i++) {
        int n = ty + i * 8;
        out[((size_t)b * N + n0 + n) * DD + c0 + tx] = tile[tx][n];
    }
}

// Wcat = [W1x | perm(W1m @ Wm)], bf = W1m@bm + b1.
// Right-half column permutation matches attn's (h*64+di) channel order:
// old channel j = di*4 + h  ->  new position (j&3)*64 + (j>>2).
__global__ void fuse_w1(const __half* __restrict__ wts, const float* __restrict__ b1,
                        const float* __restrict__ bm,
                        __half* __restrict__ wcat, float* __restrict__ bf)
{
    const __half* w1 = wts + OFF_W1;
    const __half* wm = wts + OFF_WM;
    int o = blockIdx.x, j = threadIdx.x;

    wcat[o * 512 + j] = w1[o * 512 + j];

    float acc = 0.f;
    const __half* w1m = w1 + o * 512 + 256;
    #pragma unroll 8
    for (int kk = 0; kk < 256; kk++)
        acc = fmaf(__half2float(w1m[kk]), __half2float(wm[kk * 256 + j]), acc);
    int jp = (j & 3) * 64 + (j >> 2);
    wcat[o * 512 + 256 + jp] = __float2half_rn(acc);

    if (j == 0) {
        float b = b1[o];
        for (int kk = 0; kk < 256; kk++)
            b = fmaf(__half2float(w1m[kk]), __half2float(bm[kk]), b);
        bf[o] = b;
    }
}

// ---------------------------------------------------------------------------
// fp16 flash attention; ex2.f16x2 softmax; tensor-core row sums (ones column).
// grid (N/128, H, B), 128 threads (4 warps), 32 q-rows/warp.
// Writes attn_t (B,N,256) fp16, channel = h*64 + di (contiguous, vectorized).
// ---------------------------------------------------------------------------
#define LDB   72
#define VROWS 72

__global__ void __launch_bounds__(128)
flash_attn_fp16(const __half* __restrict__ q, const __half* __restrict__ k,
                const __half* __restrict__ v, __half* __restrict__ attn,
                int N, int M)
{
    extern __shared__ char smb[];
    __half* Ks = reinterpret_cast<__half*>(smb);             // [2][64][LDB]
    __half* Vs = reinterpret_cast<__half*>(smb + 18432);     // [2][VROWS][LDB]
    __half* Qs = reinterpret_cast<__half*>(smb + 39168);     // [128][LDB]
    __half* OTh = reinterpret_cast<__half*>(smb);            // [128][72] epilogue

    const int b  = blockIdx.z, h = blockIdx.y;
    const int n0 = blockIdx.x * 128;
    const int bh = b * HH + h;
    const int t  = threadIdx.x;
    const int wid = t >> 5, lane = t & 31;
    const int g = lane >> 2, tg = lane & 3;
    const int wr = wid * 32;

    const __half* Kg = k + (size_t)bh * M * 64;
    const __half* Vg = v + (size_t)bh * 64 * M;

    // prefetch K/V tile 0
    {
        uint32_t kd = smem_u32(Ks), vd = smem_u32(Vs);
        #pragma unroll
        for (int i = 0; i < 4; i++) {
            int idx = t + i * 128;
            int r = idx >> 3, c = (idx & 7) * 8;
            cp16(kd + (uint32_t)(r * LDB + c) * 2, Kg + r * 64 + c);
            cp16(vd + (uint32_t)(r * LDB + c) * 2, Vg + (size_t)r * M + c);
        }
        CP_COMMIT();
    }

    // ones/zeros rows 64..71 of both V buffers
    {
        const __half one = __float2half(1.0f);
        const __half zer = __float2half(0.0f);
        for (int i = t; i < 2 * 8 * LDB; i += 128) {
            int buf = i / (8 * LDB);
            int rem = i - buf * 8 * LDB;
            int r = rem / LDB, c = rem - r * LDB;
            Vs[(size_t)buf * VROWS * LDB + (64 + r) * LDB + c] = (r == 0) ? one : zer;
        }
    }

    // stage Q
    {
        const __half* Qg = q + ((size_t)bh * N + n0) * 64;
        #pragma unroll
        for (int i = 0; i < 8; i++) {
            int idx = t + i * 128;
            int r = idx >> 3, c = (idx & 7) * 8;
            *reinterpret_cast<uint4*>(Qs + r * LDB + c) =
                *reinterpret_cast<const uint4*>(Qg + r * 64 + c);
        }
    }
    __syncthreads();

    // persistent Q fragments
    uint32_t Qf[2][4][4];
    #pragma unroll
    for (int mt = 0; mt < 2; mt++) {
        int r0 = wr + mt * 16 + g;
        #pragma unroll
        for (int kk = 0; kk < 4; kk++) {
            Qf[mt][kk][0] = *reinterpret_cast<uint32_t*>(Qs + (r0    ) * LDB + kk * 16 + 2 * tg);
            Qf[mt][kk][1] = *reinterpret_cast<uint32_t*>(Qs + (r0 + 8) * LDB + kk * 16 + 2 * tg);
            Qf[mt][kk][2] = *reinterpret_cast<uint32_t*>(Qs + (r0    ) * LDB + kk * 16 + 2 * tg + 8);
            Qf[mt][kk][3] = *reinterpret_cast<uint32_t*>(Qs + (r0 + 8) * LDB + kk * 16 + 2 * tg + 8);
        }
    }
    __syncthreads();

    float Of[9][2][4] = {};     // Of[8] = l accumulators via ones column

    const int nT = M / 64;
    for (int tt = 0; tt < nT; tt++) {
        const __half* Kc = Ks + (size_t)(tt & 1) * 64 * LDB;
        const __half* Vc = Vs + (size_t)(tt & 1) * VROWS * LDB;

        if (tt + 1 < nT) {
            uint32_t kd = smem_u32(Ks + (size_t)((tt + 1) & 1) * 64 * LDB);
            uint32_t vd = smem_u32(Vs + (size_t)((tt + 1) & 1) * VROWS * LDB);
            const __half* Kn = Kg + (size_t)(tt + 1) * 64 * 64;
            const __half* Vn = Vg + (size_t)(tt + 1) * 64;
            #pragma unroll
            for (int i = 0; i < 4; i++) {
                int idx = t + i * 128;
                int r = idx >> 3, c = (idx & 7) * 8;
                cp16(kd + (uint32_t)(r * LDB + c) * 2, Kn + r * 64 + c);
                cp16(vd + (uint32_t)(r * LDB + c) * 2, Vn + (size_t)r * M + c);
            }
            CP_COMMIT();
            CP_WAIT(1);
        } else {
            CP_WAIT(0);
        }
        __syncthreads();

        // S = Q K^T
        float Sc[8][2][4] = {};
        #pragma unroll
        for (int kk = 0; kk < 4; kk++) {
            #pragma unroll
            for (int j = 0; j < 8; j++) {
                const __half* Kr = Kc + (j * 8 + g) * LDB + kk * 16 + 2 * tg;
                uint32_t b0 = *reinterpret_cast<const uint32_t*>(Kr);
                uint32_t b1 = *reinterpret_cast<const uint32_t*>(Kr + 8);
                mma16f(Sc[j][0], Qf[0][kk], b0, b1);
                mma16f(Sc[j][1], Qf[1][kk], b0, b1);
            }
        }

        // exp2 f16x2 -> PV A-fragments
        uint32_t Pa[4][2][4];
        #pragma unroll
        for (int mt = 0; mt < 2; mt++) {
            #pragma unroll
            for (int j = 0; j < 8; j++) {
                int kk = j >> 1, hf = (j & 1) * 2;
                Pa[kk][mt][hf    ] = ex2h2(packh(Sc[j][mt][0], Sc[j][mt][1]));
                Pa[kk][mt][hf + 1] = ex2h2(packh(Sc[j][mt][2], Sc[j][mt][3]));
            }
        }

        // O += P V ; j=8 block accumulates l
        #pragma unroll
        for (int kk = 0; kk < 4; kk++) {
            #pragma unroll
            for (int j = 0; j < 9; j++) {
                const __half* Vr = Vc + (j * 8 + g) * LDB + kk * 16 + 2 * tg;
                uint32_t b0 = *reinterpret_cast<const uint32_t*>(Vr);
                uint32_t b1 = *reinterpret_cast<const uint32_t*>(Vr + 8);
                mma16f(Of[j][0], Pa[kk][0], b0, b1);
                mma16f(Of[j][1], Pa[kk][1], b0, b1);
            }
        }
        __syncthreads();
    }

    float linv[2][2];
    #pragma unroll
    for (int mt = 0; mt < 2; mt++) {
        float l0 = __shfl_sync(0xffffffffu, Of[8][mt][0], lane & ~3);
        float l1 = __shfl_sync(0xffffffffu, Of[8][mt][2], lane & ~3);
        linv[mt][0] = 1.0f / l0;
        linv[mt][1] = 1.0f / l1;
    }

    __syncthreads();   // K/V smem dead; reuse as OTh [128 n][72 di]
    #pragma unroll
    for (int j = 0; j < 8; j++) {
        #pragma unroll
        for (int mt = 0; mt < 2; mt++) {
            int r0 = wr + mt * 16 + g;
            *reinterpret_cast<uint32_t*>(OTh + (r0    ) * 72 + j * 8 + 2 * tg) =
                packh(Of[j][mt][0] * linv[mt][0], Of[j][mt][1] * linv[mt][0]);
            *reinterpret_cast<uint32_t*>(OTh + (r0 + 8) * 72 + j * 8 + 2 * tg) =
                packh(Of[j][mt][2] * linv[mt][1], Of[j][mt][3] * linv[mt][1]);
        }
    }
    __syncthreads();

    // vectorized store: attn_t[(b*N + n0+n)*256 + h*64 + di]
    __half* Ag = attn + ((size_t)b * N + n0) * DD + h * 64;
    #pragma unroll
    for (int it = 0; it < 8; it++) {
        int n = it * 16 + (t >> 3);
        int qd = (t & 7) * 8;
        uint4 val = *reinterpret_cast<const uint4*>(OTh + n * 72 + qd);
        *reinterpret_cast<uint4*>(Ag + (size_t)n * DD + qd) = val;
    }
}

// ---------------------------------------------------------------------------
// fp16 GEMM body: out[o][n] = sum_k W[o][k] * Xt[n][k].
// Tile 128x128, BK=32, double-buffered cp.async; 8 warps = 2(o) x 4(n),
// warp tile 64x32. Both tiles [128][LDH] k-contiguous fp16.
// ---------------------------------------------------------------------------
#define LDH 40   // halves pitch (20 words: conflict-free for (g*20+tg)%32)

struct GemmOut {
    float acc[4][4][4];
    int o0, n0, wo, wn, g, tg;
};

__device__ __forceinline__ void gemm_body_h(
    const __half* __restrict__ W, const __half* __restrict__ X0, int S0, int C0,
    const __half* __restrict__ X1, int S1, int b, int IC, int N,
    int o0, int n0, __half* sm, GemmOut& R)
{
    __half* Ws = sm;                   // [2][128][LDH]
    __half* Xs = sm + 2 * 128 * LDH;   // [2][128][LDH]

    const int t  = threadIdx.x;
    const int wid = t >> 5, lane = t & 31;
    R.g = lane >> 2; R.tg = lane & 3;
    R.wo = (wid & 1) * 64;
    R.wn = (wid >> 1) * 32;
    R.o0 = o0; R.n0 = n0;

    auto stage = [&](int buf, int k0) {
        uint32_t wd = smem_u32(Ws + buf * 128 * LDH);
        uint32_t xd = smem_u32(Xs + buf * 128 * LDH);
        #pragma unroll
        for (int i = 0; i < 2; i++) {
            int idx = t + i * 256;
            int r = idx >> 2, c = (idx & 3) * 8;
            cp16(wd + (uint32_t)(r * LDH + c) * 2, W + (size_t)(o0 + r) * IC + k0 + c);
        }
        const __half* xb; int S;
        if (k0 < C0) { xb = X0 + (size_t)b * N * S0 + k0;        S = S0; }
        else         { xb = X1 + (size_t)b * N * S1 + (k0 - C0); S = S1; }
        #pragma unroll
        for (int i = 0; i < 2; i++) {
            int idx = t + i * 256;
            int r = idx >> 2, c = (idx & 3) * 8;
            cp16(xd + (uint32_t)(r * LDH + c) * 2, xb + (size_t)(n0 + r) * S + c);
        }
        CP_COMMIT();
    };

    stage(0, 0);
    #pragma unroll
    for (int a = 0; a < 4; a++)
        #pragma unroll
        for (int c = 0; c < 4; c++)
            #pragma unroll
            for (int d = 0; d < 4; d++) R.acc[a][c][d] = 0.f;

    const int nK = IC / 32;
    for (int kt = 0; kt < nK; kt++) {
        if (kt + 1 < nK) { stage((kt + 1) & 1, (kt + 1) * 32); CP_WAIT(1); }
        else             { CP_WAIT(0); }
        __syncthreads();
        const __half* Wc = Ws + (kt & 1) * 128 * LDH;
        const __half* Xc = Xs + (kt & 1) * 128 * LDH;

        #pragma unroll
        for (int ks = 0; ks < 2; ks++) {
            uint32_t Af[4][4];
            #pragma unroll
            for (int mt = 0; mt < 4; mt++) {
                int r0 = R.wo + mt * 16 + R.g;
                Af[mt][0] = *reinterpret_cast<const uint32_t*>(Wc + (r0    ) * LDH + ks * 16 + 2 * R.tg);
                Af[mt][1] = *reinterpret_cast<const uint32_t*>(Wc + (r0 + 8) * LDH + ks * 16 + 2 * R.tg);
                Af[mt][2] = *reinterpret_cast<const uint32_t*>(Wc + (r0    ) * LDH + ks * 16 + 2 * R.tg + 8);
                Af[mt][3] = *reinterpret_cast<const uint32_t*>(Wc + (r0 + 8) * LDH + ks * 16 + 2 * R.tg + 8);
            }
            #pragma unroll
            for (int nt = 0; nt < 4; nt++) {
                const __half* Xr = Xc + (R.wn + nt * 8 + R.g) * LDH + ks * 16 + 2 * R.tg;
                uint32_t b0 = *reinterpret_cast<const uint32_t*>(Xr);
                uint32_t b1 = *reinterpret_cast<const uint32_t*>(Xr + 8);
                #pragma unroll
                for (int mt = 0; mt < 4; mt++)
                    mma16f(R.acc[mt][nt], Af[mt], b0, b1);
            }
        }
        __syncthreads();
    }
}

// generic projection. mode 0: fp32 (B,OC,N); mode 1: fp16 (B,OC,N).
__global__ void __launch_bounds__(256)
gemm_h(const __half* __restrict__ W, const float* __restrict__ bias,
       const __half* __restrict__ X0, int S0, int C0,
       const __half* __restrict__ X1, int S1,
       void* __restrict__ out, int OC, int IC, int N, int mode)
{
    extern __shared__ __half smh[];
    GemmOut R;
    gemm_body_h(W, X0, S0, C0, X1, S1, blockIdx.z, IC, N,
                blockIdx.y * 128, blockIdx.x * 128, smh, R);

    #pragma unroll
    for (int mt = 0; mt < 4; mt++) {
        int o_g  = R.o0 + R.wo + mt * 16 + R.g;
        int o_g8 = o_g + 8;
        float bg  = bias[o_g];
        float bg8 = bias[o_g8];
        #pragma unroll
        for (int nt = 0; nt < 4; nt++) {
            int n = R.n0 + R.wn + nt * 8 + 2 * R.tg;
            float c0 = R.acc[mt][nt][0] + bg,  c1 = R.acc[mt][nt][1] + bg;
            float c2 = R.acc[mt][nt][2] + bg8, c3 = R.acc[mt][nt][3] + bg8;
            if (mode == 0) {
                float* o32 = (float*)out;
                *reinterpret_cast<float2*>(o32 + ((size_t)blockIdx.z * OC + o_g ) * N + n) =
                    make_float2(c0, c1);
                *reinterpret_cast<float2*>(o32 + ((size_t)blockIdx.z * OC + o_g8) * N + n) =
                    make_float2(c2, c3);
            } else {
                __half* o16 = (__half*)out;
                *reinterpret_cast<uint32_t*>(o16 + ((size_t)blockIdx.z * OC + o_g ) * N + n) =
                    packh(c0, c1);
                *reinterpret_cast<uint32_t*>(o16 + ((size_t)blockIdx.z * OC + o_g8) * N + n) =
                    packh(c2, c3);
            }
        }
    }
}

// fused Q/K/V projection: grid (N/128, 2, 6); z = which*2 + b.
__global__ void __launch_bounds__(256)
gemm_qkv(const __half* __restrict__ wts,
         const float* __restrict__ bq, const float* __restrict__ bk,
         const float* __restrict__ bv,
         const __half* __restrict__ xt, const __half* __restrict__ st,
         __half* __restrict__ qp, __half* __restrict__ kp,
         __half* __restrict__ vp, int N)
{
    extern __shared__ __half smh[];
    const int z = blockIdx.z;
    const int which = z >> 1;
    const int b = z & 1;
    const __half* W    = wts + which * 65536;
    const float* bias  = (which == 0) ? bq : (which == 1) ? bk : bv;
    const __half* X    = (which == 0) ? xt : st;
    const float oscale = (which == 0) ? QSCALE : 1.0f;

    GemmOut R;
    gemm_body_h(W, X, DD, DD, nullptr, DD, b, DD, N,
                blockIdx.y * 128, blockIdx.x * 128, smh, R);

    #pragma unroll
    for (int mt = 0; mt < 4; mt++) {
        int o_g  = R.o0 + R.wo + mt * 16 + R.g;
        int o_g8 = o_g + 8;
        float bg  = bias[o_g];
        float bg8 = bias[o_g8];
        #pragma unroll
        for (int nt = 0; nt < 4; nt++) {
            int n = R.n0 + R.wn + nt * 8 + 2 * R.tg;
            float c0 = (R.acc[mt][nt][0] + bg)  * oscale;
            float c1 = (R.acc[mt][nt][1] + bg)  * oscale;
            float c2 = (R.acc[mt][nt][2] + bg8) * oscale;
            float c3 = (R.acc[mt][nt][3] + bg8) * oscale;
            int h0 = o_g & 3,  d0 = o_g >> 2;
            int h1 = o_g8 & 3, d1 = o_g8 >> 2;
            if (which < 2) {
                __half* out = (which == 0) ? qp : kp;
                out[(((size_t)b * HH + h0) * N + n    ) * 64 + d0] = __float2half_rn(c0);
                out[(((size_t)b * HH + h0) * N + n + 1) * 64 + d0] = __float2half_rn(c1);
                out[(((size_t)b * HH + h1) * N + n    ) * 64 + d1] = __float2half_rn(c2);
                out[(((size_t)b * HH + h1) * N + n + 1) * 64 + d1] = __float2half_rn(c3);
            } else {
                *reinterpret_cast<uint32_t*>(
                    vp + (((size_t)b * HH + h0) * 64 + d0) * N + n) = packh(c0, c1);
                *reinterpret_cast<uint32_t*>(
                    vp + (((size_t)b * HH + h1) * 64 + d1) * N + n) = packh(c2, c3);
            }
        }
    }
}

// ---------------------------------------------------------------------------
// InstanceNorm stats: per (b,c) row of h (B,2D,N) fp16 -> mean, inv.
// ---------------------------------------------------------------------------
__global__ void inst_stats(const __half* __restrict__ hb, float* __restrict__ stats, int N)
{
    int row = blockIdx.x;
    const __half* p = hb + (size_t)row * N;

    float s = 0.f, s2 = 0.f;
    for (int i = threadIdx.x * 8; i < N; i += 256 * 8) {
        uint4 raw = *reinterpret_cast<const uint4*>(p + i);
        const __half2* h2 = reinterpret_cast<const __half2*>(&raw);
        #pragma unroll
        for (int kk = 0; kk < 4; kk++) {
            float2 f = __half22float2(h2[kk]);
            s  += f.x + f.y;
            s2 += f.x * f.x + f.y * f.y;
        }
    }
    #pragma unroll
    for (int off = 16; off > 0; off >>= 1) {
        s  += __shfl_xor_sync(0xffffffffu, s,  off);
        s2 += __shfl_xor_sync(0xffffffffu, s2, off);
    }
    __shared__ float sh[16];
    int wid = threadIdx.x >> 5, lid = threadIdx.x & 31;
    if (lid == 0) { sh[wid] = s; sh[wid + 8] = s2; }
    __syncthreads();
    if (threadIdx.x == 0) {
        s = 0.f; s2 = 0.f;
        #pragma unroll
        for (int w = 0; w < 8; w++) { s += sh[w]; s2 += sh[w + 8]; }
        float mean = s / (float)N;
        float var  = s2 / (float)N - mean * mean;
        stats[row * 2]     = mean;
        stats[row * 2 + 1] = rsqrtf(var + 1e-5f);
    }
}

// normalize + ReLU + transpose: h (B,2D,N) fp16 -> ht (B,N,512) fp16.
// grid (N/32, 512/32, B), block 256 (32x8).
__global__ void norm_transpose(const __half* __restrict__ hb, const float* __restrict__ stats,
                               __half* __restrict__ ht, int N)
{
    __shared__ __half tile[32][33];
    const int b = blockIdx.z;
    const int c0 = blockIdx.y * 32, n0 = blockIdx.x * 32;
    const int tx = threadIdx.x & 31, ty = threadIdx.x >> 5;

    #pragma unroll
    for (int i = 0; i < 4; i++) {
        int c = ty + i * 8;
        int row = b * 512 + c0 + c;
        float mu  = stats[row * 2];
        float inv = stats[row * 2 + 1];
        float v = __half2float(hb[(size_t)row * N + n0 + tx]);
        tile[c][tx] = __float2half_rn(fmaxf(0.f, (v - mu) * inv));
    }
    __syncthreads();
    #pragma unroll
    for (int i = 0; i < 4; i++) {
        int n = ty + i * 8;
        ht[((size_t)b * N + n0 + n) * 512 + c0 + tx] = tile[tx][n];
    }
}

// ---------------------------------------------------------------------------
extern "C" void kernel_launch(void* const* d_in, const int* in_sizes, int n_in,
                              void* d_out, int out_size)
{
    const float* x   = (const float*)d_in[0];
    const float* src = (const float*)d_in[1];
    const float* Wq  = (const float*)d_in[2];
    const float* bq  = (const float*)d_in[3];
    const float* Wk  = (const float*)d_in[4];
    const float* bk  = (const float*)d_in[5];
    const float* Wv  = (const float*)d_in[6];
    const float* bv  = (const float*)d_in[7];
    const float* Wm  = (const float*)d_in[8];
    const float* bm  = (const float*)d_in[9];
    const float* W1  = (const float*)d_in[10];
    const float* b1  = (const float*)d_in[11];
    const float* W2  = (const float*)d_in[12];
    const float* b2  = (const float*)d_in[13];

    const int B = BB, D = DD;
    const int N = in_sizes[0] / (B * D);
    const int M = in_sizes[1] / (B * D);

    __half *qp, *kp, *vp, *xtp, *stp, *attnp, *hp, *htp, *wts, *wcat;
    float *bf, *stats;
    cudaGetSymbolAddress((void**)&qp,    g_q);
    cudaGetSymbolAddress((void**)&kp,    g_k);
    cudaGetSymbolAddress((void**)&vp,    g_v);
    cudaGetSymbolAddress((void**)&xtp,   g_xt);
    cudaGetSymbolAddress((void**)&stp,   g_st);
    cudaGetSymbolAddress((void**)&attnp, g_attn);
    cudaGetSymbolAddress((void**)&hp,    g_h);
    cudaGetSymbolAddress((void**)&htp,   g_ht);
    cudaGetSymbolAddress((void**)&wts,   g_wts);
    cudaGetSymbolAddress((void**)&wcat,  g_wcat);
    cudaGetSymbolAddress((void**)&bf,    g_bf);
    cudaGetSymbolAddress((void**)&stats, g_stats);

    const int gsmem = 4 * 128 * LDH * (int)sizeof(__half);   // 40960
    const int fsmem = 18432 + 20736 + 18432;                  // 57600
    cudaFuncSetAttribute(gemm_h,   cudaFuncAttributeMaxDynamicSharedMemorySize, gsmem);
    cudaFuncSetAttribute(gemm_qkv, cudaFuncAttributeMaxDynamicSharedMemorySize, gsmem);
    cudaFuncSetAttribute(flash_attn_fp16, cudaFuncAttributeMaxDynamicSharedMemorySize, fsmem);

    // 0. producers
    round_weights<<<(655360 + 255) / 256, 256>>>(Wq, Wk, Wv, Wm, W1, W2, wts);
    transpose_in<<<dim3(N / 32, D / 32, 2 * B), 256>>>(x, src, xtp, stp, N);
    fuse_w1<<<512, 256>>>(wts, b1, bm, wcat, bf);

    // 1. fused Q/K/V projections
    gemm_qkv<<<dim3(N / 128, D / 128, 3 * B), 256, gsmem>>>(
        wts, bq, bk, bv, xtp, stp, qp, kp, vp, N);

    // 2. fp16 flash attention -> attn_t (B,N,256)
    flash_attn_fp16<<<dim3(N / 128, HH, B), 128, fsmem>>>(qp, kp, vp, attnp, N, M);

    // 3. fused W1 layer -> h (B,2D,N) fp16
    gemm_h<<<dim3(N / 128, (2 * D) / 128, B), 256, gsmem>>>(
        wcat, bf, xtp, D, D, attnp, D, hp, 2 * D, 2 * D, N, 1);

    // 4. InstanceNorm stats + normalize/transpose -> ht (B,N,512)
    inst_stats<<<B * 2 * D, 256>>>(hp, stats, N);
    norm_transpose<<<dim3(N / 32, (2 * D) / 32, B), 256>>>(hp, stats, htp, N);

    // 5. final projection -> d_out (B,D,N) fp32
    gemm_h<<<dim3(N / 128, D / 128, B), 256, gsmem>>>(
        wts + OFF_W2, b2, htp, 2 * D, 2 * D, nullptr, 2 * D, d_out, D, 2 * D, N, 0);
}

// round 11
// speedup vs baseline: 1.3396x; 1.1119x over previous
#include <cuda_runtime.h>
#include <cuda_fp16.h>
#include <cstdint>
#include <cstddef>

// ---------------------------------------------------------------------------
// AttentionalPropagation, B=2, D=256, H=4, dim=64, N=M=4096.
// R11: ldmatrix fragment loads everywhere; smem-staged coalesced q/k epilogue.
// ---------------------------------------------------------------------------

#define BB 2
#define DD 256
#define HH 4

__device__ __half g_q[BB * HH * 4096 * 64];   // [b][h][n][di], pre-scaled
__device__ __half g_k[BB * HH * 4096 * 64];   // [b][h][m][di]
__device__ __half g_v[BB * HH * 64 * 4096];   // [b][h][di][m] (transposed)
__device__ __half g_xt  [BB * 4096 * DD];     // x  transposed (B,N,256) fp16
__device__ __half g_st  [BB * 4096 * DD];     // src transposed
__device__ __half g_attn[BB * 4096 * DD];     // attn (B,N,256), ch = h*64+di
__device__ __half g_h   [BB * 2 * DD * 4096]; // (B,2D,N) fp16 (pre-norm)
__device__ __half g_ht  [BB * 4096 * 2 * DD]; // (B,N,512) fp16 (post-norm)
__device__ __half g_wts [655360];             // fp16 weights
__device__ __half g_wcat[512 * 512];          // [W1x | perm(W1m@Wm)] fp16
__device__ float  g_bf  [512];                // W1m@bm + b1
__device__ float  g_stats[BB * 2 * DD * 2];   // per (b,c): mean, inv

#define OFF_WQ 0
#define OFF_WK 65536
#define OFF_WV 131072
#define OFF_WM 196608
#define OFF_W1 262144
#define OFF_W2 524288

#define QSCALE (0.125f * 1.44269504088896340736f)

// ============================ PTX helpers ==================================
__device__ __forceinline__ uint32_t smem_u32(const void* p) {
    uint32_t a;
    asm("{ .reg .u64 t; cvta.to.shared.u64 t, %1; cvt.u32.u64 %0, t; }"
        : "=r"(a) : "l"(p));
    return a;
}
__device__ __forceinline__ uint32_t packh(float lo, float hi) {
    __half2 h = __floats2half2_rn(lo, hi);
    return *reinterpret_cast<uint32_t*>(&h);
}
__device__ __forceinline__ uint32_t ex2h2(uint32_t h2) {
    uint32_t r; asm("ex2.approx.f16x2 %0, %1;" : "=r"(r) : "r"(h2)); return r;
}
__device__ __forceinline__ void mma16f(float* d, const uint32_t* a,
                                       uint32_t b0, uint32_t b1) {
    asm volatile("mma.sync.aligned.m16n8k16.row.col.f32.f16.f16.f32 "
        "{%0,%1,%2,%3}, {%4,%5,%6,%7}, {%8,%9}, {%0,%1,%2,%3};"
        : "+f"(d[0]), "+f"(d[1]), "+f"(d[2]), "+f"(d[3])
        : "r"(a[0]), "r"(a[1]), "r"(a[2]), "r"(a[3]), "r"(b0), "r"(b1));
}
__device__ __forceinline__ void ldsm4(uint32_t* r, uint32_t addr) {
    asm volatile("ldmatrix.sync.aligned.m8n8.x4.shared.b16 {%0,%1,%2,%3}, [%4];"
        : "=r"(r[0]), "=r"(r[1]), "=r"(r[2]), "=r"(r[3]) : "r"(addr));
}
__device__ __forceinline__ void cp16(uint32_t s, const void* g) {
    asm volatile("cp.async.ca.shared.global [%0], [%1], 16;" :: "r"(s), "l"(g));
}
#define CP_COMMIT() asm volatile("cp.async.commit_group;" ::: "memory")
#define CP_WAIT(n)  asm volatile("cp.async.wait_group %0;" :: "n"(n) : "memory")

// ---------------------------------------------------------------------------
// producers
// ---------------------------------------------------------------------------
__global__ void round_weights(const float* __restrict__ wq, const float* __restrict__ wk,
                              const float* __restrict__ wv, const float* __restrict__ wm,
                              const float* __restrict__ w1, const float* __restrict__ w2,
                              __half* __restrict__ dst)
{
    int i = blockIdx.x * 256 + threadIdx.x;
    if (i >= 655360) return;
    float v;
    if      (i < OFF_WK) v = wq[i - OFF_WQ];
    else if (i < OFF_WV) v = wk[i - OFF_WK];
    else if (i < OFF_WM) v = wv[i - OFF_WV];
    else if (i < OFF_W1) v = wm[i - OFF_WM];
    else if (i < OFF_W2) v = w1[i - OFF_W1];
    else                 v = w2[i - OFF_W2];
    dst[i] = __float2half_rn(v);
}

__global__ void transpose_in(const float* __restrict__ x, const float* __restrict__ src,
                             __half* __restrict__ xt, __half* __restrict__ st, int N)
{
    __shared__ __half tile[32][33];
    const int which = blockIdx.z >> 1, b = blockIdx.z & 1;
    const float* in = which ? src : x;
    __half* out = which ? st : xt;
    const int c0 = blockIdx.y * 32, n0 = blockIdx.x * 32;
    const int tx = threadIdx.x & 31, ty = threadIdx.x >> 5;

    #pragma unroll
    for (int i = 0; i < 4; i++) {
        int c = ty + i * 8;
        tile[c][tx] = __float2half_rn(in[((size_t)(b * DD + c0 + c)) * N + n0 + tx]);
    }
    __syncthreads();
    #pragma unroll
    for (int i = 0; i < 4; i++) {
        int n = ty + i * 8;
        out[((size_t)b * N + n0 + n) * DD + c0 + tx] = tile[tx][n];
    }
}

__global__ void fuse_w1(const __half* __restrict__ wts, const float* __restrict__ b1,
                        const float* __restrict__ bm,
                        __half* __restrict__ wcat, float* __restrict__ bf)
{
    const __half* w1 = wts + OFF_W1;
    const __half* wm = wts + OFF_WM;
    int o = blockIdx.x, j = threadIdx.x;

    wcat[o * 512 + j] = w1[o * 512 + j];

    float acc = 0.f;
    const __half* w1m = w1 + o * 512 + 256;
    #pragma unroll 8
    for (int kk = 0; kk < 256; kk++)
        acc = fmaf(__half2float(w1m[kk]), __half2float(wm[kk * 256 + j]), acc);
    int jp = (j & 3) * 64 + (j >> 2);
    wcat[o * 512 + 256 + jp] = __float2half_rn(acc);

    if (j == 0) {
        float b = b1[o];
        for (int kk = 0; kk < 256; kk++)
            b = fmaf(__half2float(w1m[kk]), __half2float(bm[kk]), b);
        bf[o] = b;
    }
}

// ---------------------------------------------------------------------------
// fp16 flash attention; ldmatrix K/V loads; ex2.f16x2 softmax; tensor row-sum.
// grid (N/128, H, B), 128 threads (4 warps), 32 q-rows/warp.
// ---------------------------------------------------------------------------
#define LDB   72
#define VROWS 72

__global__ void __launch_bounds__(128)
flash_attn_fp16(const __half* __restrict__ q, const __half* __restrict__ k,
                const __half* __restrict__ v, __half* __restrict__ attn,
                int N, int M)
{
    extern __shared__ char smb[];
    __half* Ks = reinterpret_cast<__half*>(smb);             // [2][64][LDB]
    __half* Vs = reinterpret_cast<__half*>(smb + 18432);     // [2][VROWS][LDB]
    __half* Qs = reinterpret_cast<__half*>(smb + 39168);     // [128][LDB]
    __half* OTh = reinterpret_cast<__half*>(smb);            // [128][72] epilogue

    const int b  = blockIdx.z, h = blockIdx.y;
    const int n0 = blockIdx.x * 128;
    const int bh = b * HH + h;
    const int t  = threadIdx.x;
    const int wid = t >> 5, lane = t & 31;
    const int g = lane >> 2, tg = lane & 3;
    const int wr = wid * 32;
    // ldmatrix lane offsets (B-pattern: rows, 8-col groups)
    const int lrow = lane & 7;
    const int lcol = (lane >> 3) * 8;

    const __half* Kg = k + (size_t)bh * M * 64;
    const __half* Vg = v + (size_t)bh * 64 * M;

    {
        uint32_t kd = smem_u32(Ks), vd = smem_u32(Vs);
        #pragma unroll
        for (int i = 0; i < 4; i++) {
            int idx = t + i * 128;
            int r = idx >> 3, c = (idx & 7) * 8;
            cp16(kd + (uint32_t)(r * LDB + c) * 2, Kg + r * 64 + c);
            cp16(vd + (uint32_t)(r * LDB + c) * 2, Vg + (size_t)r * M + c);
        }
        CP_COMMIT();
    }

    // ones/zeros rows 64..71 of both V buffers
    {
        const __half one = __float2half(1.0f);
        const __half zer = __float2half(0.0f);
        for (int i = t; i < 2 * 8 * LDB; i += 128) {
            int buf = i / (8 * LDB);
            int rem = i - buf * 8 * LDB;
            int r = rem / LDB, c = rem - r * LDB;
            Vs[(size_t)buf * VROWS * LDB + (64 + r) * LDB + c] = (r == 0) ? one : zer;
        }
    }

    // stage Q
    {
        const __half* Qg = q + ((size_t)bh * N + n0) * 64;
        #pragma unroll
        for (int i = 0; i < 8; i++) {
            int idx = t + i * 128;
            int r = idx >> 3, c = (idx & 7) * 8;
            *reinterpret_cast<uint4*>(Qs + r * LDB + c) =
                *reinterpret_cast<const uint4*>(Qg + r * 64 + c);
        }
    }
    __syncthreads();

    // persistent Q fragments
    uint32_t Qf[2][4][4];
    #pragma unroll
    for (int mt = 0; mt < 2; mt++) {
        int r0 = wr + mt * 16 + g;
        #pragma unroll
        for (int kk = 0; kk < 4; kk++) {
            Qf[mt][kk][0] = *reinterpret_cast<uint32_t*>(Qs + (r0    ) * LDB + kk * 16 + 2 * tg);
            Qf[mt][kk][1] = *reinterpret_cast<uint32_t*>(Qs + (r0 + 8) * LDB + kk * 16 + 2 * tg);
            Qf[mt][kk][2] = *reinterpret_cast<uint32_t*>(Qs + (r0    ) * LDB + kk * 16 + 2 * tg + 8);
            Qf[mt][kk][3] = *reinterpret_cast<uint32_t*>(Qs + (r0 + 8) * LDB + kk * 16 + 2 * tg + 8);
        }
    }
    __syncthreads();

    float Of[9][2][4] = {};     // Of[8] = l accumulators via ones column

    const int nT = M / 64;
    for (int tt = 0; tt < nT; tt++) {
        const __half* Kc = Ks + (size_t)(tt & 1) * 64 * LDB;
        const __half* Vc = Vs + (size_t)(tt & 1) * VROWS * LDB;

        if (tt + 1 < nT) {
            uint32_t kd = smem_u32(Ks + (size_t)((tt + 1) & 1) * 64 * LDB);
            uint32_t vd = smem_u32(Vs + (size_t)((tt + 1) & 1) * VROWS * LDB);
            const __half* Kn = Kg + (size_t)(tt + 1) * 64 * 64;
            const __half* Vn = Vg + (size_t)(tt + 1) * 64;
            #pragma unroll
            for (int i = 0; i < 4; i++) {
                int idx = t + i * 128;
                int r = idx >> 3, c = (idx & 7) * 8;
                cp16(kd + (uint32_t)(r * LDB + c) * 2, Kn + r * 64 + c);
                cp16(vd + (uint32_t)(r * LDB + c) * 2, Vn + (size_t)r * M + c);
            }
            CP_COMMIT();
            CP_WAIT(1);
        } else {
            CP_WAIT(0);
        }
        __syncthreads();

        const uint32_t kb = smem_u32(Kc);
        const uint32_t vb = smem_u32(Vc);

        // S = Q K^T  (ldmatrix, j pairs, kk-inner: 4-way mma ILP)
        float Sc[8][2][4] = {};
        #pragma unroll
        for (int jp = 0; jp < 4; jp++) {
            uint32_t Kf[2][8];
            #pragma unroll
            for (int jj = 0; jj < 2; jj++) {
                uint32_t a = kb + (uint32_t)(((jp * 2 + jj) * 8 + lrow) * LDB + lcol) * 2;
                ldsm4(Kf[jj],     a);
                ldsm4(Kf[jj] + 4, a + 64);
            }
            #pragma unroll
            for (int kk = 0; kk < 4; kk++) {
                mma16f(Sc[jp * 2    ][0], Qf[0][kk], Kf[0][kk * 2], Kf[0][kk * 2 + 1]);
                mma16f(Sc[jp * 2    ][1], Qf[1][kk], Kf[0][kk * 2], Kf[0][kk * 2 + 1]);
                mma16f(Sc[jp * 2 + 1][0], Qf[0][kk], Kf[1][kk * 2], Kf[1][kk * 2 + 1]);
                mma16f(Sc[jp * 2 + 1][1], Qf[1][kk], Kf[1][kk * 2], Kf[1][kk * 2 + 1]);
            }
        }

        // exp2 f16x2 -> PV A-fragments
        uint32_t Pa[4][2][4];
        #pragma unroll
        for (int mt = 0; mt < 2; mt++) {
            #pragma unroll
            for (int j = 0; j < 8; j++) {
                int kk = j >> 1, hf = (j & 1) * 2;
                Pa[kk][mt][hf    ] = ex2h2(packh(Sc[j][mt][0], Sc[j][mt][1]));
                Pa[kk][mt][hf + 1] = ex2h2(packh(Sc[j][mt][2], Sc[j][mt][3]));
            }
        }

        // O += P V (ldmatrix, j pairs) ; j=8 = ones rows -> l
        #pragma unroll
        for (int jp = 0; jp < 4; jp++) {
            uint32_t Vf[2][8];
            #pragma unroll
            for (int jj = 0; jj < 2; jj++) {
                uint32_t a = vb + (uint32_t)(((jp * 2 + jj) * 8 + lrow) * LDB + lcol) * 2;
                ldsm4(Vf[jj],     a);
                ldsm4(Vf[jj] + 4, a + 64);
            }
            #pragma unroll
            for (int kk = 0; kk < 4; kk++) {
                mma16f(Of[jp * 2    ][0], Pa[kk][0], Vf[0][kk * 2], Vf[0][kk * 2 + 1]);
                mma16f(Of[jp * 2    ][1], Pa[kk][1], Vf[0][kk * 2], Vf[0][kk * 2 + 1]);
                mma16f(Of[jp * 2 + 1][0], Pa[kk][0], Vf[1][kk * 2], Vf[1][kk * 2 + 1]);
                mma16f(Of[jp * 2 + 1][1], Pa[kk][1], Vf[1][kk * 2], Vf[1][kk * 2 + 1]);
            }
        }
        {
            uint32_t Vf8[8];
            uint32_t a = vb + (uint32_t)((64 + lrow) * LDB + lcol) * 2;
            ldsm4(Vf8,     a);
            ldsm4(Vf8 + 4, a + 64);
            #pragma unroll
            for (int kk = 0; kk < 4; kk++) {
                mma16f(Of[8][0], Pa[kk][0], Vf8[kk * 2], Vf8[kk * 2 + 1]);
                mma16f(Of[8][1], Pa[kk][1], Vf8[kk * 2], Vf8[kk * 2 + 1]);
            }
        }
        __syncthreads();
    }

    float linv[2][2];
    #pragma unroll
    for (int mt = 0; mt < 2; mt++) {
        float l0 = __shfl_sync(0xffffffffu, Of[8][mt][0], lane & ~3);
        float l1 = __shfl_sync(0xffffffffu, Of[8][mt][2], lane & ~3);
        linv[mt][0] = 1.0f / l0;
        linv[mt][1] = 1.0f / l1;
    }

    __syncthreads();   // K/V smem dead; reuse as OTh [128 n][72 di]
    #pragma unroll
    for (int j = 0; j < 8; j++) {
        #pragma unroll
        for (int mt = 0; mt < 2; mt++) {
            int r0 = wr + mt * 16 + g;
            *reinterpret_cast<uint32_t*>(OTh + (r0    ) * 72 + j * 8 + 2 * tg) =
                packh(Of[j][mt][0] * linv[mt][0], Of[j][mt][1] * linv[mt][0]);
            *reinterpret_cast<uint32_t*>(OTh + (r0 + 8) * 72 + j * 8 + 2 * tg) =
                packh(Of[j][mt][2] * linv[mt][1], Of[j][mt][3] * linv[mt][1]);
        }
    }
    __syncthreads();

    __half* Ag = attn + ((size_t)b * N + n0) * DD + h * 64;
    #pragma unroll
    for (int it = 0; it < 8; it++) {
        int n = it * 16 + (t >> 3);
        int qd = (t & 7) * 8;
        uint4 val = *reinterpret_cast<const uint4*>(OTh + n * 72 + qd);
        *reinterpret_cast<uint4*>(Ag + (size_t)n * DD + qd) = val;
    }
}

// ---------------------------------------------------------------------------
// fp16 GEMM body with ldmatrix fragment loads.
// Tile 128x128, BK=32; 8 warps = 2(o) x 4(n), warp tile 64x32.
// ---------------------------------------------------------------------------
#define LDH 40

struct GemmOut {
    float acc[4][4][4];
    int o0, n0, wo, wn, g, tg;
};

__device__ __forceinline__ void gemm_body_h(
    const __half* __restrict__ W, const __half* __restrict__ X0, int S0, int C0,
    const __half* __restrict__ X1, int S1, int b, int IC, int N,
    int o0, int n0, __half* sm, GemmOut& R)
{
    __half* Ws = sm;                   // [2][128][LDH]
    __half* Xs = sm + 2 * 128 * LDH;   // [2][128][LDH]

    const int t  = threadIdx.x;
    const int wid = t >> 5, lane = t & 31;
    R.g = lane >> 2; R.tg = lane & 3;
    R.wo = (wid & 1) * 64;
    R.wn = (wid >> 1) * 32;
    R.o0 = o0; R.n0 = n0;
    // ldmatrix lane offsets
    const int a_row = (lane & 7) + ((lane >> 3) & 1) * 8;
    const int a_col = (lane >> 4) * 8;
    const int b_row = lane & 7;
    const int b_col = (lane >> 3) * 8;

    auto stage = [&](int buf, int k0) {
        uint32_t wd = smem_u32(Ws + buf * 128 * LDH);
        uint32_t xd = smem_u32(Xs + buf * 128 * LDH);
        #pragma unroll
        for (int i = 0; i < 2; i++) {
            int idx = t + i * 256;
            int r = idx >> 2, c = (idx & 3) * 8;
            cp16(wd + (uint32_t)(r * LDH + c) * 2, W + (size_t)(o0 + r) * IC + k0 + c);
        }
        const __half* xb; int S;
        if (k0 < C0) { xb = X0 + (size_t)b * N * S0 + k0;        S = S0; }
        else         { xb = X1 + (size_t)b * N * S1 + (k0 - C0); S = S1; }
        #pragma unroll
        for (int i = 0; i < 2; i++) {
            int idx = t + i * 256;
            int r = idx >> 2, c = (idx & 3) * 8;
            cp16(xd + (uint32_t)(r * LDH + c) * 2, xb + (size_t)(n0 + r) * S + c);
        }
        CP_COMMIT();
    };

    stage(0, 0);
    #pragma unroll
    for (int a = 0; a < 4; a++)
        #pragma unroll
        for (int c = 0; c < 4; c++)
            #pragma unroll
            for (int d = 0; d < 4; d++) R.acc[a][c][d] = 0.f;

    const int nK = IC / 32;
    for (int kt = 0; kt < nK; kt++) {
        if (kt + 1 < nK) { stage((kt + 1) & 1, (kt + 1) * 32); CP_WAIT(1); }
        else             { CP_WAIT(0); }
        __syncthreads();
        const uint32_t wb = smem_u32(Ws + (kt & 1) * 128 * LDH);
        const uint32_t xb = smem_u32(Xs + (kt & 1) * 128 * LDH);

        uint32_t Bf[4][4];
        #pragma unroll
        for (int nt = 0; nt < 4; nt++)
            ldsm4(Bf[nt], xb + (uint32_t)((R.wn + nt * 8 + b_row) * LDH + b_col) * 2);

        #pragma unroll
        for (int ks = 0; ks < 2; ks++) {
            uint32_t Af[4][4];
            #pragma unroll
            for (int mt = 0; mt < 4; mt++)
                ldsm4(Af[mt], wb + (uint32_t)((R.wo + mt * 16 + a_row) * LDH
                                              + ks * 16 + a_col) * 2);
            #pragma unroll
            for (int nt = 0; nt < 4; nt++)
                #pragma unroll
                for (int mt = 0; mt < 4; mt++)
                    mma16f(R.acc[mt][nt], Af[mt], Bf[nt][ks * 2], Bf[nt][ks * 2 + 1]);
        }
        __syncthreads();
    }
}

// generic projection. mode 0: fp32 (B,OC,N); mode 1: fp16 (B,OC,N).
__global__ void __launch_bounds__(256)
gemm_h(const __half* __restrict__ W, const float* __restrict__ bias,
       const __half* __restrict__ X0, int S0, int C0,
       const __half* __restrict__ X1, int S1,
       void* __restrict__ out, int OC, int IC, int N, int mode)
{
    extern __shared__ __half smh[];
    GemmOut R;
    gemm_body_h(W, X0, S0, C0, X1, S1, blockIdx.z, IC, N,
                blockIdx.y * 128, blockIdx.x * 128, smh, R);

    #pragma unroll
    for (int mt = 0; mt < 4; mt++) {
        int o_g  = R.o0 + R.wo + mt * 16 + R.g;
        int o_g8 = o_g + 8;
        float bg  = bias[o_g];
        float bg8 = bias[o_g8];
        #pragma unroll
        for (int nt = 0; nt < 4; nt++) {
            int n = R.n0 + R.wn + nt * 8 + 2 * R.tg;
            float c0 = R.acc[mt][nt][0] + bg,  c1 = R.acc[mt][nt][1] + bg;
            float c2 = R.acc[mt][nt][2] + bg8, c3 = R.acc[mt][nt][3] + bg8;
            if (mode == 0) {
                float* o32 = (float*)out;
                *reinterpret_cast<float2*>(o32 + ((size_t)blockIdx.z * OC + o_g ) * N + n) =
                    make_float2(c0, c1);
                *reinterpret_cast<float2*>(o32 + ((size_t)blockIdx.z * OC + o_g8) * N + n) =
                    make_float2(c2, c3);
            } else {
                __half* o16 = (__half*)out;
                *reinterpret_cast<uint32_t*>(o16 + ((size_t)blockIdx.z * OC + o_g ) * N + n) =
                    packh(c0, c1);
                *reinterpret_cast<uint32_t*>(o16 + ((size_t)blockIdx.z * OC + o_g8) * N + n) =
                    packh(c2, c3);
            }
        }
    }
}

// fused Q/K/V projection with smem-staged coalesced epilogue for q/k.
// grid (N/128, D/128, 6); z = which*2 + b.
__global__ void __launch_bounds__(256)
gemm_qkv(const __half* __restrict__ wts,
         const float* __restrict__ bq, const float* __restrict__ bk,
         const float* __restrict__ bv,
         const __half* __restrict__ xt, const __half* __restrict__ st,
         __half* __restrict__ qp, __half* __restrict__ kp,
         __half* __restrict__ vp, int N)
{
    extern __shared__ __half smh[];
    const int z = blockIdx.z;
    const int which = z >> 1;
    const int b = z & 1;
    const __half* W    = wts + which * 65536;
    const float* bias  = (which == 0) ? bq : (which == 1) ? bk : bv;
    const __half* X    = (which == 0) ? xt : st;
    const float oscale = (which == 0) ? QSCALE : 1.0f;

    GemmOut R;
    gemm_body_h(W, X, DD, DD, nullptr, DD, b, DD, N,
                blockIdx.y * 128, blockIdx.x * 128, smh, R);

    const int t = threadIdx.x;

    if (which < 2) {
        // stage to smem: [n_local][ (o&3)*32 + (o>>2 local) ], pitch 136
        __half* St = smh;
        __syncthreads();   // smem free after mainloop's final barrier is passed by all
        #pragma unroll
        for (int mt = 0; mt < 4; mt++) {
            int ol  = R.wo + mt * 16 + R.g;
            int ol8 = ol + 8;
            float bg  = bias[R.o0 + ol];
            float bg8 = bias[R.o0 + ol8];
            int col  = (ol  & 3) * 32 + (ol  >> 2);
            int col8 = (ol8 & 3) * 32 + (ol8 >> 2);
            #pragma unroll
            for (int nt = 0; nt < 4; nt++) {
                int nl = R.wn + nt * 8 + 2 * R.tg;
                St[(nl    ) * 136 + col ] = __float2half_rn((R.acc[mt][nt][0] + bg)  * oscale);
                St[(nl + 1) * 136 + col ] = __float2half_rn((R.acc[mt][nt][1] + bg)  * oscale);
                St[(nl    ) * 136 + col8] = __float2half_rn((R.acc[mt][nt][2] + bg8) * oscale);
                St[(nl + 1) * 136 + col8] = __float2half_rn((R.acc[mt][nt][3] + bg8) * oscale);
            }
        }
        __syncthreads();

        // coalesced 16B stores: out[((b*H+h)*N + n0+nl)*64 + di0 + quad*8]
        __half* out = (which == 0) ? qp : kp;
        const int di0 = R.o0 >> 2;
        #pragma unroll
        for (int it = 0; it < 8; it++) {
            int idx = t + it * 256;
            int quad = idx & 3, pr = idx >> 2;     // pr 0..511
            int hh = pr >> 7, nl = pr & 127;
            uint4 val = *reinterpret_cast<const uint4*>(St + nl * 136 + hh * 32 + quad * 8);
            *reinterpret_cast<uint4*>(
                out + (((size_t)b * HH + hh) * N + R.n0 + nl) * 64 + di0 + quad * 8) = val;
        }
    } else {
        // V: transposed [b][h][di][m]; packed 4B stores along n (already decent)
        #pragma unroll
        for (int mt = 0; mt < 4; mt++) {
            int o_g  = R.o0 + R.wo + mt * 16 + R.g;
            int o_g8 = o_g + 8;
            float bg  = bias[o_g];
            float bg8 = bias[o_g8];
            #pragma unroll
            for (int nt = 0; nt < 4; nt++) {
                int n = R.n0 + R.wn + nt * 8 + 2 * R.tg;
                int h0 = o_g & 3,  d0 = o_g >> 2;
                int h1 = o_g8 & 3, d1 = o_g8 >> 2;
                *reinterpret_cast<uint32_t*>(
                    vp + (((size_t)b * HH + h0) * 64 + d0) * N + n) =
                    packh(R.acc[mt][nt][0] + bg, R.acc[mt][nt][1] + bg);
                *reinterpret_cast<uint32_t*>(
                    vp + (((size_t)b * HH + h1) * 64 + d1) * N + n) =
                    packh(R.acc[mt][nt][2] + bg8, R.acc[mt][nt][3] + bg8);
            }
        }
    }
}

// ---------------------------------------------------------------------------
// InstanceNorm stats + normalize/transpose
// ---------------------------------------------------------------------------
__global__ void inst_stats(const __half* __restrict__ hb, float* __restrict__ stats, int N)
{
    int row = blockIdx.x;
    const __half* p = hb + (size_t)row * N;

    float s = 0.f, s2 = 0.f;
    for (int i = threadIdx.x * 8; i < N; i += 256 * 8) {
        uint4 raw = *reinterpret_cast<const uint4*>(p + i);
        const __half2* h2 = reinterpret_cast<const __half2*>(&raw);
        #pragma unroll
        for (int kk = 0; kk < 4; kk++) {
            float2 f = __half22float2(h2[kk]);
            s  += f.x + f.y;
            s2 += f.x * f.x + f.y * f.y;
        }
    }
    #pragma unroll
    for (int off = 16; off > 0; off >>= 1) {
        s  += __shfl_xor_sync(0xffffffffu, s,  off);
        s2 += __shfl_xor_sync(0xffffffffu, s2, off);
    }
    __shared__ float sh[16];
    int wid = threadIdx.x >> 5, lid = threadIdx.x & 31;
    if (lid == 0) { sh[wid] = s; sh[wid + 8] = s2; }
    __syncthreads();
    if (threadIdx.x == 0) {
        s = 0.f; s2 = 0.f;
        #pragma unroll
        for (int w = 0; w < 8; w++) { s += sh[w]; s2 += sh[w + 8]; }
        float mean = s / (float)N;
        float var  = s2 / (float)N - mean * mean;
        stats[row * 2]     = mean;
        stats[row * 2 + 1] = rsqrtf(var + 1e-5f);
    }
}

__global__ void norm_transpose(const __half* __restrict__ hb, const float* __restrict__ stats,
                               __half* __restrict__ ht, int N)
{
    __shared__ __half tile[32][33];
    const int b = blockIdx.z;
    const int c0 = blockIdx.y * 32, n0 = blockIdx.x * 32;
    const int tx = threadIdx.x & 31, ty = threadIdx.x >> 5;

    #pragma unroll
    for (int i = 0; i < 4; i++) {
        int c = ty + i * 8;
        int row = b * 512 + c0 + c;
        float mu  = stats[row * 2];
        float inv = stats[row * 2 + 1];
        float v = __half2float(hb[(size_t)row * N + n0 + tx]);
        tile[c][tx] = __float2half_rn(fmaxf(0.f, (v - mu) * inv));
    }
    __syncthreads();
    #pragma unroll
    for (int i = 0; i < 4; i++) {
        int n = ty + i * 8;
        ht[((size_t)b * N + n0 + n) * 512 + c0 + tx] = tile[tx][n];
    }
}

// ---------------------------------------------------------------------------
extern "C" void kernel_launch(void* const* d_in, const int* in_sizes, int n_in,
                              void* d_out, int out_size)
{
    const float* x   = (const float*)d_in[0];
    const float* src = (const float*)d_in[1];
    const float* Wq  = (const float*)d_in[2];
    const float* bq  = (const float*)d_in[3];
    const float* Wk  = (const float*)d_in[4];
    const float* bk  = (const float*)d_in[5];
    const float* Wv  = (const float*)d_in[6];
    const float* bv  = (const float*)d_in[7];
    const float* Wm  = (const float*)d_in[8];
    const float* bm  = (const float*)d_in[9];
    const float* W1  = (const float*)d_in[10];
    const float* b1  = (const float*)d_in[11];
    const float* W2  = (const float*)d_in[12];
    const float* b2  = (const float*)d_in[13];

    const int B = BB, D = DD;
    const int N = in_sizes[0] / (B * D);
    const int M = in_sizes[1] / (B * D);

    __half *qp, *kp, *vp, *xtp, *stp, *attnp, *hp, *htp, *wts, *wcat;
    float *bf, *stats;
    cudaGetSymbolAddress((void**)&qp,    g_q);
    cudaGetSymbolAddress((void**)&kp,    g_k);
    cudaGetSymbolAddress((void**)&vp,    g_v);
    cudaGetSymbolAddress((void**)&xtp,   g_xt);
    cudaGetSymbolAddress((void**)&stp,   g_st);
    cudaGetSymbolAddress((void**)&attnp, g_attn);
    cudaGetSymbolAddress((void**)&hp,    g_h);
    cudaGetSymbolAddress((void**)&htp,   g_ht);
    cudaGetSymbolAddress((void**)&wts,   g_wts);
    cudaGetSymbolAddress((void**)&wcat,  g_wcat);
    cudaGetSymbolAddress((void**)&bf,    g_bf);
    cudaGetSymbolAddress((void**)&stats, g_stats);

    const int gsmem = 4 * 128 * LDH * (int)sizeof(__half);   // 40960
    const int fsmem = 18432 + 20736 + 18432;                  // 57600
    cudaFuncSetAttribute(gemm_h,   cudaFuncAttributeMaxDynamicSharedMemorySize, gsmem);
    cudaFuncSetAttribute(gemm_qkv, cudaFuncAttributeMaxDynamicSharedMemorySize, gsmem);
    cudaFuncSetAttribute(flash_attn_fp16, cudaFuncAttributeMaxDynamicSharedMemorySize, fsmem);

    // 0. producers
    round_weights<<<(655360 + 255) / 256, 256>>>(Wq, Wk, Wv, Wm, W1, W2, wts);
    transpose_in<<<dim3(N / 32, D / 32, 2 * B), 256>>>(x, src, xtp, stp, N);
    fuse_w1<<<512, 256>>>(wts, b1, bm, wcat, bf);

    // 1. fused Q/K/V projections
    gemm_qkv<<<dim3(N / 128, D / 128, 3 * B), 256, gsmem>>>(
        wts, bq, bk, bv, xtp, stp, qp, kp, vp, N);

    // 2. fp16 flash attention -> attn_t (B,N,256)
    flash_attn_fp16<<<dim3(N / 128, HH, B), 128, fsmem>>>(qp, kp, vp, attnp, N, M);

    // 3. fused W1 layer -> h (B,2D,N) fp16
    gemm_h<<<dim3(N / 128, (2 * D) / 128, B), 256, gsmem>>>(
        wcat, bf, xtp, D, D, attnp, D, hp, 2 * D, 2 * D, N, 1);

    // 4. InstanceNorm stats + normalize/transpose -> ht (B,N,512)
    inst_stats<<<B * 2 * D, 256>>>(hp, stats, N);
    norm_transpose<<<dim3(N / 32, (2 * D) / 32, B), 256>>>(hp, stats, htp, N);

    // 5. final projection -> d_out (B,D,N) fp32
    gemm_h<<<dim3(N / 128, D / 128, B), 256, gsmem>>>(
        wts + OFF_W2, b2, htp, 2 * D, 2 * D, nullptr, 2 * D, d_out, D, 2 * D, N, 0);
}